// round 14
// baseline (speedup 1.0000x reference)
#include <cuda_runtime.h>
#include <cstdint>
#include <math.h>

#define SEQ   2048
#define NG    16            // B*H "heads" after the plain reshape
#define HD    64
#define EMB   512
#define QSCALE 0.1803368801111204f   // 0.125 * log2(e): folds softmax scale + exp -> exp2

#define BQ 256              // q rows per CTA (8 warps x 32 rows)
#define BK 64               // keys per tile
#define NKT (SEQ/BK)        // 32 key tiles
#define PITCH 72            // smem row pitch in bf16 elems (144B: conflict-free frags)
#define PITCHB 144u

// ---- scratch (pre-split bf16 hi + residual-lo pairs) ----
__device__ __align__(16) uint16_t g_Qh [NG*SEQ*HD];
__device__ __align__(16) uint16_t g_Ql [NG*SEQ*HD];
__device__ __align__(16) uint16_t g_Kh [NG*SEQ*HD];
__device__ __align__(16) uint16_t g_Kl [NG*SEQ*HD];
__device__ __align__(16) uint16_t g_Vth[NG*HD*SEQ];   // [g][d][s]
__device__ __align__(16) uint16_t g_Vtl[NG*HD*SEQ];
__device__ __align__(16) uint16_t g_Ah [NG*SEQ*HD];   // attention out, flat [4096][512]
__device__ __align__(16) uint16_t g_Al [NG*SEQ*HD];
__device__ __align__(16) uint16_t g_Wh [EMB*EMB];
__device__ __align__(16) uint16_t g_Wl [EMB*EMB];

// ---- helpers ----
__device__ __forceinline__ void split2(float x0, float x1, uint32_t& h, uint32_t& l){
    asm("cvt.rn.bf16x2.f32 %0, %1, %2;" : "=r"(h) : "f"(x1), "f"(x0));
    float h0 = __uint_as_float(h << 16);
    float h1 = __uint_as_float(h & 0xffff0000u);
    float l0 = x0 - h0, l1 = x1 - h1;
    asm("cvt.rn.bf16x2.f32 %0, %1, %2;" : "=r"(l) : "f"(l1), "f"(l0));
}
__device__ __forceinline__ void mma_bf16(float* d, const uint32_t* a, const uint32_t* b){
    asm volatile("mma.sync.aligned.m16n8k16.row.col.f32.bf16.bf16.f32 "
        "{%0,%1,%2,%3}, {%4,%5,%6,%7}, {%8,%9}, {%0,%1,%2,%3};"
        : "+f"(d[0]), "+f"(d[1]), "+f"(d[2]), "+f"(d[3])
        : "r"(a[0]), "r"(a[1]), "r"(a[2]), "r"(a[3]), "r"(b[0]), "r"(b[1]));
}
__device__ __forceinline__ float ex2(float x){
    float r; asm("ex2.approx.f32 %0, %1;" : "=f"(r) : "f"(x)); return r;
}
__device__ __forceinline__ uint32_t smem_u32(const void* p){
    uint32_t a;
    asm("{ .reg .u64 t; cvta.to.shared.u64 t, %1; cvt.u32.u64 %0, t; }" : "=r"(a) : "l"(p));
    return a;
}
#define LDSM4(r, a) \
    asm volatile("ldmatrix.sync.aligned.m8n8.x4.shared.b16 {%0,%1,%2,%3}, [%4];" \
        : "=r"((r)[0]), "=r"((r)[1]), "=r"((r)[2]), "=r"((r)[3]) : "r"(a))
__device__ __forceinline__ void cp16(uint32_t dst, const void* src){
    asm volatile("cp.async.cg.shared.global [%0], [%1], 16;" :: "r"(dst), "l"(src));
}
#define CP_COMMIT() asm volatile("cp.async.commit_group;" ::: "memory")
#define CP_WAIT(n)  asm volatile("cp.async.wait_group %0;" :: "n"(n) : "memory")

// scalar-LDS frag loads (proj)
__device__ __forceinline__ void lda(uint32_t* a, const char* base, uint32_t off){
    a[0] = *(const uint32_t*)(base + off);
    a[1] = *(const uint32_t*)(base + off + PITCH*16u);
    a[2] = *(const uint32_t*)(base + off + 16u);
    a[3] = *(const uint32_t*)(base + off + PITCH*16u + 16u);
}
__device__ __forceinline__ void ldb(uint32_t* b, const char* base, uint32_t off){
    b[0] = *(const uint32_t*)(base + off);
    b[1] = *(const uint32_t*)(base + off + 16u);
}

// attn smem: QH[256x144] QL | K/V double buffer
#define QH_O 0u
#define QL_O 36864u
#define KV_O 73728u
#define KVB  36864u        // per buffer: KH 0 | KL 9216 | VH 18432 | VL 27648
#define SMEM_ATT 147456u

// proj smem
#define PJ_XH 0u
#define PJ_XL 18432u
#define PJ_WH 36864u
#define PJ_WL 46080u
#define PJ_BYTES 55296u

// fc smem (128x128 tile): per buffer AH 0 | AL 18432 | BH 36864 | BL 55296
#define FC_AH 0u
#define FC_AL 18432u
#define FC_BH 36864u
#define FC_BL 55296u
#define FC_BUF 73728u
#define FC_BYTES 147456u

// ---------------------------------------------------------------------------
__global__ void wsplit_k(const float* __restrict__ W)
{
    int i = (blockIdx.x*256 + threadIdx.x)*4;
    float4 x = *(const float4*)&W[i];
    uint32_t h0,l0,h1,l1;
    split2(x.x, x.y, h0, l0); split2(x.z, x.w, h1, l1);
    *(uint2*)&((uint32_t*)g_Wh)[i>>1] = make_uint2(h0,h1);
    *(uint2*)&((uint32_t*)g_Wl)[i>>1] = make_uint2(l0,l1);
}

// ---------------------------------------------------------------------------
// QKV projection via mma
// ---------------------------------------------------------------------------
__global__ __launch_bounds__(256) void proj_k(
    const float* __restrict__ q, const float* __restrict__ k, const float* __restrict__ v,
    const float* __restrict__ Wq, const float* __restrict__ Wk, const float* __restrict__ Wv)
{
    extern __shared__ __align__(16) char smem[];
    const int t    = threadIdx.x;
    const int lane = t & 31, wid = t >> 5;
    const int r4 = lane >> 2, c2 = lane & 3;
    const int m0 = (wid >> 1) * 32;
    const int n0 = (wid & 1) * 32;
    const int which = blockIdx.y;
    const float* X = which==0 ? q  : (which==1 ? k  : v);
    const float* W = which==0 ? Wq : (which==1 ? Wk : Wv);
    const size_t rb = (size_t)blockIdx.x * 128;

    {
        const int row = t >> 1, cg = (t & 1) * 32;
        const float* src = X + (rb + row)*HD + cg;
        #pragma unroll
        for (int j=0;j<8;j++){
            float4 x = *(const float4*)&src[j*4];
            uint32_t h0,l0,h1,l1;
            split2(x.x, x.y, h0, l0); split2(x.z, x.w, h1, l1);
            uint32_t off = (uint32_t)(row*PITCH + cg + j*4)*2u;
            *(uint2*)(smem + PJ_XH + off) = make_uint2(h0,h1);
            *(uint2*)(smem + PJ_XL + off) = make_uint2(l0,l1);
        }
    }
    {
        const int row = t >> 2, cg = (t & 3) * 16;
        const float* src = W + row*HD + cg;
        #pragma unroll
        for (int j=0;j<4;j++){
            float4 x = *(const float4*)&src[j*4];
            uint32_t h0,l0,h1,l1;
            split2(x.x, x.y, h0, l0); split2(x.z, x.w, h1, l1);
            uint32_t off = (uint32_t)(row*PITCH + cg + j*4)*2u;
            *(uint2*)(smem + PJ_WH + off) = make_uint2(h0,h1);
            *(uint2*)(smem + PJ_WL + off) = make_uint2(l0,l1);
        }
    }
    __syncthreads();

    float acc[2][4][4] = {};
    #pragma unroll
    for (int ksz=0; ksz<4; ksz++){
        const int kc = ksz*16;
        uint32_t ah[2][4], al[2][4], bh[4][2], bl[4][2];
        #pragma unroll
        for (int mf=0; mf<2; mf++){
            uint32_t off = (uint32_t)((m0+16*mf+r4)*PITCH + kc + 2*c2)*2u;
            lda(ah[mf], smem + PJ_XH, off);
            lda(al[mf], smem + PJ_XL, off);
        }
        #pragma unroll
        for (int nf=0; nf<4; nf++){
            uint32_t off = (uint32_t)((n0+8*nf+r4)*PITCH + kc + 2*c2)*2u;
            ldb(bh[nf], smem + PJ_WH, off);
            ldb(bl[nf], smem + PJ_WL, off);
        }
        #pragma unroll
        for (int mf=0; mf<2; mf++)
            #pragma unroll
            for (int nf=0; nf<4; nf++){
                mma_bf16(acc[mf][nf], ah[mf], bh[nf]);
                mma_bf16(acc[mf][nf], ah[mf], bl[nf]);
                mma_bf16(acc[mf][nf], al[mf], bh[nf]);
            }
    }

    if (which == 2){
        __syncthreads();
        float* tile = (float*)smem;
        #pragma unroll
        for (int mf=0; mf<2; mf++)
            #pragma unroll
            for (int nf=0; nf<4; nf++){
                int rl = m0 + 16*mf + r4;
                int col = n0 + 8*nf + 2*c2;
                tile[rl*65 + col]       = acc[mf][nf][0];
                tile[rl*65 + col+1]     = acc[mf][nf][1];
                tile[(rl+8)*65 + col]   = acc[mf][nf][2];
                tile[(rl+8)*65 + col+1] = acc[mf][nf][3];
            }
        __syncthreads();
        const int g  = (int)(rb >> 11);
        const int s0 = (int)(rb & 2047);
        const int d  = t >> 2, sq = (t & 3) * 32;
        const size_t base = ((size_t)g*HD + d)*SEQ + s0 + sq;
        #pragma unroll
        for (int j8=0; j8<4; j8++){
            float f[8];
            #pragma unroll
            for (int i=0;i<8;i++) f[i] = tile[(sq + j8*8 + i)*65 + d];
            uint32_t h[4], l[4];
            split2(f[0],f[1],h[0],l[0]); split2(f[2],f[3],h[1],l[1]);
            split2(f[4],f[5],h[2],l[2]); split2(f[6],f[7],h[3],l[3]);
            *(uint4*)&((uint32_t*)g_Vth)[(base + j8*8)>>1] = make_uint4(h[0],h[1],h[2],h[3]);
            *(uint4*)&((uint32_t*)g_Vtl)[(base + j8*8)>>1] = make_uint4(l[0],l[1],l[2],l[3]);
        }
    } else {
        uint32_t* dh = (uint32_t*)(which==0 ? g_Qh : g_Kh);
        uint32_t* dl = (uint32_t*)(which==0 ? g_Ql : g_Kl);
        const float sc = (which==0) ? QSCALE : 1.0f;
        #pragma unroll
        for (int mf=0; mf<2; mf++)
            #pragma unroll
            for (int nf=0; nf<4; nf++){
                int row = (int)rb + m0 + 16*mf + r4;
                int col = n0 + 8*nf + 2*c2;
                uint32_t h, l;
                split2(acc[mf][nf][0]*sc, acc[mf][nf][1]*sc, h, l);
                size_t idx = ((size_t)row*HD + col) >> 1;
                dh[idx] = h; dl[idx] = l;
                split2(acc[mf][nf][2]*sc, acc[mf][nf][3]*sc, h, l);
                idx = ((size_t)(row+8)*HD + col) >> 1;
                dh[idx] = h; dl[idx] = l;
            }
    }
}

// ---------------------------------------------------------------------------
// Flash attention (R10 version — best measured): 8 warps x 32 q-rows,
// register P, cp.async double-buffered K/V, K/V frags shared across
// row-groups. grid = (8, 16), 256 threads, 1 CTA/SM.
// ---------------------------------------------------------------------------
__global__ __launch_bounds__(256, 1) void attn_k()
{
    extern __shared__ __align__(16) char smem[];
    const uint32_t sb = smem_u32(smem);
    const int t    = threadIdx.x;
    const int lane = t & 31, wid = t >> 5;
    const int r4 = lane >> 2, c2 = lane & 3;
    const int m0 = wid * 32;
    const int g  = blockIdx.y;
    const int q0 = blockIdx.x * BQ;

    const uint32_t a_off0 = (uint32_t)(m0 + (lane & 15)) * PITCHB + ((lane & 16) ? 16u : 0u);
    const uint32_t a_off1 = a_off0 + 16u*PITCHB;
    const uint32_t b_off  = (uint32_t)((lane & 7) + ((lane & 16) ? 8 : 0)) * PITCHB
                          + ((lane & 8) ? 16u : 0u);

    // per-thread cp.async coordinates for K/V tiles
    const int krow = t >> 2, kc = (t & 3) * 16;
    const uint32_t dko = (uint32_t)(krow*PITCH + kc)*2u;

    // ---- issue tile 0 ----
    {
        const size_t kg = (size_t)(g*SEQ + krow)*HD + kc;
        const size_t vg = ((size_t)g*HD + krow)*SEQ + kc;
        uint32_t d = sb + KV_O + dko;
        cp16(d,            g_Kh  + kg); cp16(d + 16u,          g_Kh  + kg + 8);
        cp16(d + 9216u,    g_Kl  + kg); cp16(d + 9216u + 16u,  g_Kl  + kg + 8);
        cp16(d + 18432u,   g_Vth + vg); cp16(d + 18432u + 16u, g_Vth + vg + 8);
        cp16(d + 27648u,   g_Vtl + vg); cp16(d + 27648u + 16u, g_Vtl + vg + 8);
        CP_COMMIT();
    }

    // ---- load Q tile (256 rows, one FULL 128B row per thread) ----
    {
        const uint16_t* qh = g_Qh + ((size_t)(g*SEQ + q0 + t))*HD;
        const uint16_t* ql = g_Ql + ((size_t)(g*SEQ + q0 + t))*HD;
        uint32_t off = (uint32_t)t * PITCHB;
        #pragma unroll
        for (int j=0;j<8;j++){
            *(uint4*)(smem + QH_O + off + j*16u) = *(const uint4*)(qh + j*8);
            *(uint4*)(smem + QL_O + off + j*16u) = *(const uint4*)(ql + j*8);
        }
    }

    float oacc[2][8][4] = {};
    float ls[2][2] = {};

    for (int kt = 0; kt < NKT; kt++){
        // issue next tile into the other buffer
        if (kt + 1 < NKT){
            const size_t kg = (size_t)(g*SEQ + (kt+1)*BK + krow)*HD + kc;
            const size_t vg = ((size_t)g*HD + krow)*SEQ + (kt+1)*BK + kc;
            uint32_t d = sb + KV_O + ((kt+1)&1)*KVB + dko;
            cp16(d,            g_Kh  + kg); cp16(d + 16u,          g_Kh  + kg + 8);
            cp16(d + 9216u,    g_Kl  + kg); cp16(d + 9216u + 16u,  g_Kl  + kg + 8);
            cp16(d + 18432u,   g_Vth + vg); cp16(d + 18432u + 16u, g_Vth + vg + 8);
            cp16(d + 27648u,   g_Vtl + vg); cp16(d + 27648u + 16u, g_Vtl + vg + 8);
            CP_COMMIT();
            CP_WAIT(1);
        } else {
            CP_WAIT(0);
        }
        __syncthreads();   // tile kt visible (and Q on first iter)

        const uint32_t kvb = sb + KV_O + (kt&1)*KVB;

        // ---- S = Q K^T: K frags loaded once, feed both row groups ----
        float sacc[2][8][4] = {};
        #pragma unroll
        for (int ksz=0; ksz<4; ksz++){
            const uint32_t kb = (uint32_t)ksz * 32u;
            uint32_t qh0[4], ql0[4], qh1[4], ql1[4];
            LDSM4(qh0, sb + QH_O + a_off0 + kb);
            LDSM4(ql0, sb + QL_O + a_off0 + kb);
            LDSM4(qh1, sb + QH_O + a_off1 + kb);
            LDSM4(ql1, sb + QL_O + a_off1 + kb);
            #pragma unroll
            for (int np=0; np<4; np++){
                uint32_t bh[4], bl[4];
                LDSM4(bh, kvb + (uint32_t)np*2304u + b_off + kb);
                LDSM4(bl, kvb + 9216u + (uint32_t)np*2304u + b_off + kb);
                mma_bf16(sacc[0][2*np  ], qh0, bh);
                mma_bf16(sacc[0][2*np  ], qh0, bl);
                mma_bf16(sacc[0][2*np  ], ql0, bh);
                mma_bf16(sacc[0][2*np+1], qh0, bh+2);
                mma_bf16(sacc[0][2*np+1], qh0, bl+2);
                mma_bf16(sacc[0][2*np+1], ql0, bh+2);
                mma_bf16(sacc[1][2*np  ], qh1, bh);
                mma_bf16(sacc[1][2*np  ], qh1, bl);
                mma_bf16(sacc[1][2*np  ], ql1, bh);
                mma_bf16(sacc[1][2*np+1], qh1, bh+2);
                mma_bf16(sacc[1][2*np+1], qh1, bl+2);
                mma_bf16(sacc[1][2*np+1], ql1, bh+2);
            }
        }

        // ---- fused softmax + PV per 16-key chunk ----
        #pragma unroll
        for (int ks2=0; ks2<4; ks2++){
            uint32_t pah[2][4], pal[2][4];
            #pragma unroll
            for (int mg=0; mg<2; mg++){
                #pragma unroll
                for (int j=0;j<2;j++){
                    const int nf = 2*ks2 + j;
                    float p0 = ex2(sacc[mg][nf][0]), p1 = ex2(sacc[mg][nf][1]);
                    float p2 = ex2(sacc[mg][nf][2]), p3 = ex2(sacc[mg][nf][3]);
                    ls[mg][0] += p0 + p1;
                    ls[mg][1] += p2 + p3;
                    split2(p0, p1, pah[mg][2*j  ], pal[mg][2*j  ]);
                    split2(p2, p3, pah[mg][2*j+1], pal[mg][2*j+1]);
                }
            }
            const uint32_t kb = (uint32_t)ks2 * 32u;
            #pragma unroll
            for (int np=0; np<4; np++){
                uint32_t bh[4], bl[4];
                LDSM4(bh, kvb + 18432u + (uint32_t)np*2304u + b_off + kb);
                LDSM4(bl, kvb + 27648u + (uint32_t)np*2304u + b_off + kb);
                #pragma unroll
                for (int mg=0; mg<2; mg++){
                    mma_bf16(oacc[mg][2*np  ], pah[mg], bh);
                    mma_bf16(oacc[mg][2*np  ], pah[mg], bl);
                    mma_bf16(oacc[mg][2*np  ], pal[mg], bh);
                    mma_bf16(oacc[mg][2*np+1], pah[mg], bh+2);
                    mma_bf16(oacc[mg][2*np+1], pah[mg], bl+2);
                    mma_bf16(oacc[mg][2*np+1], pal[mg], bh+2);
                }
            }
        }
        __syncthreads();   // buf[kt&1] reads done -> next iter may refill it
    }

    // ---- row sums over c2 lanes ----
    #pragma unroll
    for (int mg=0; mg<2; mg++)
        #pragma unroll
        for (int i=0;i<2;i++){
            ls[mg][i] += __shfl_xor_sync(0xffffffffu, ls[mg][i], 1);
            ls[mg][i] += __shfl_xor_sync(0xffffffffu, ls[mg][i], 2);
        }

    // ---- write O / lsum, pre-split for fc ----
    uint32_t* ah32 = (uint32_t*)g_Ah;
    uint32_t* al32 = (uint32_t*)g_Al;
    #pragma unroll
    for (int mg=0; mg<2; mg++){
        const int row = q0 + m0 + mg*16 + r4;
        const float inv0 = 1.0f / ls[mg][0], inv1 = 1.0f / ls[mg][1];
        #pragma unroll
        for (int nf=0; nf<8; nf++){
            int col = 8*nf + 2*c2;
            uint32_t h, l;
            split2(oacc[mg][nf][0]*inv0, oacc[mg][nf][1]*inv0, h, l);
            size_t idx = (((size_t)(g*SEQ + row))*HD + col) >> 1;
            ah32[idx] = h; al32[idx] = l;
            split2(oacc[mg][nf][2]*inv1, oacc[mg][nf][3]*inv1, h, l);
            idx = (((size_t)(g*SEQ + row + 8))*HD + col) >> 1;
            ah32[idx] = h; al32[idx] = l;
        }
    }
}

// ---------------------------------------------------------------------------
// FC: 128x128 output tiles -> grid (4, 32) = 128 CTAs = ONE full wave.
// 8 warps (4m x 2n), warp tile 32x64 (8 independent accum chains = ILP).
// cp.async double-buffered chunks. out = att @ Wfc^T + bfc.
// ---------------------------------------------------------------------------
__global__ __launch_bounds__(256, 1) void fc_k(const float* __restrict__ bfc,
                                               float* __restrict__ out)
{
    extern __shared__ __align__(16) char smem[];
    const uint32_t sb = smem_u32(smem);
    const int t    = threadIdx.x;
    const int lane = t & 31, wid = t >> 5;
    const int r4 = lane >> 2, c2 = lane & 3;
    const int m0 = (wid >> 1) * 32;
    const int n0 = (wid & 1) * 64;
    const int eb = blockIdx.x * 128;
    const size_t rb = (size_t)blockIdx.y * 128;

    const uint32_t a_off0 = (uint32_t)(m0 + (lane & 15)) * PITCHB + ((lane & 16) ? 16u : 0u);
    const uint32_t a_off1 = a_off0 + 16u*PITCHB;
    const uint32_t b_off  = (uint32_t)(n0 + (lane & 7) + ((lane & 16) ? 8 : 0)) * PITCHB
                          + ((lane & 8) ? 16u : 0u);

    // per-thread cp.async coordinates (A and B both 128 rows x 64 k)
    const int arow = t >> 1, acg = (t & 1) * 32;
    const uint32_t dao = (uint32_t)(arow*PITCH + acg)*2u;

    // issue chunk 0
    {
        const uint16_t* ah = g_Ah + (rb + arow)*EMB + acg;
        const uint16_t* al = g_Al + (rb + arow)*EMB + acg;
        const uint16_t* bh = g_Wh + (size_t)(eb + arow)*EMB + acg;
        const uint16_t* bl = g_Wl + (size_t)(eb + arow)*EMB + acg;
        #pragma unroll
        for (int j=0;j<4;j++){
            cp16(sb + FC_AH + dao + j*16u, ah + j*8);
            cp16(sb + FC_AL + dao + j*16u, al + j*8);
            cp16(sb + FC_BH + dao + j*16u, bh + j*8);
            cp16(sb + FC_BL + dao + j*16u, bl + j*8);
        }
        CP_COMMIT();
    }

    float acc[2][8][4] = {};

    for (int kc2 = 0; kc2 < 8; kc2++){
        if (kc2 + 1 < 8){
            const int f1 = (kc2+1) * 64;
            const uint16_t* ah = g_Ah + (rb + arow)*EMB + f1 + acg;
            const uint16_t* al = g_Al + (rb + arow)*EMB + f1 + acg;
            const uint16_t* bh = g_Wh + (size_t)(eb + arow)*EMB + f1 + acg;
            const uint16_t* bl = g_Wl + (size_t)(eb + arow)*EMB + f1 + acg;
            uint32_t d = sb + ((kc2+1)&1)*FC_BUF;
            #pragma unroll
            for (int j=0;j<4;j++){
                cp16(d + FC_AH + dao + j*16u, ah + j*8);
                cp16(d + FC_AL + dao + j*16u, al + j*8);
                cp16(d + FC_BH + dao + j*16u, bh + j*8);
                cp16(d + FC_BL + dao + j*16u, bl + j*8);
            }
            CP_COMMIT();
            CP_WAIT(1);
        } else {
            CP_WAIT(0);
        }
        __syncthreads();   // chunk kc2 visible

        const uint32_t buf = sb + (kc2&1)*FC_BUF;

        #pragma unroll
        for (int ksz=0; ksz<4; ksz++){
            const uint32_t kb = (uint32_t)ksz * 32u;
            uint32_t ah0[4], al0[4], ah1[4], al1[4];
            LDSM4(ah0, buf + FC_AH + a_off0 + kb);
            LDSM4(al0, buf + FC_AL + a_off0 + kb);
            LDSM4(ah1, buf + FC_AH + a_off1 + kb);
            LDSM4(al1, buf + FC_AL + a_off1 + kb);
            #pragma unroll
            for (int np=0; np<4; np++){
                uint32_t bh[4], bl[4];
                LDSM4(bh, buf + FC_BH + (uint32_t)np*(16u*PITCHB) + b_off + kb);
                LDSM4(bl, buf + FC_BL + (uint32_t)np*(16u*PITCHB) + b_off + kb);
                mma_bf16(acc[0][2*np  ], ah0, bh);
                mma_bf16(acc[0][2*np  ], ah0, bl);
                mma_bf16(acc[0][2*np  ], al0, bh);
                mma_bf16(acc[0][2*np+1], ah0, bh+2);
                mma_bf16(acc[0][2*np+1], ah0, bl+2);
                mma_bf16(acc[0][2*np+1], al0, bh+2);
                mma_bf16(acc[1][2*np  ], ah1, bh);
                mma_bf16(acc[1][2*np  ], ah1, bl);
                mma_bf16(acc[1][2*np  ], al1, bh);
                mma_bf16(acc[1][2*np+1], ah1, bh+2);
                mma_bf16(acc[1][2*np+1], ah1, bl+2);
                mma_bf16(acc[1][2*np+1], al1, bh+2);
            }
        }
        __syncthreads();   // buf reads done -> next iter may refill it
    }

    #pragma unroll
    for (int mf=0; mf<2; mf++)
        #pragma unroll
        for (int nf=0; nf<8; nf++){
            int row = (int)rb + m0 + 16*mf + r4;
            int col = eb + n0 + 8*nf + 2*c2;
            float2 b = *(const float2*)&bfc[col];
            *(float2*)&out[(size_t)row*EMB + col] =
                make_float2(acc[mf][nf][0]+b.x, acc[mf][nf][1]+b.y);
            *(float2*)&out[(size_t)(row+8)*EMB + col] =
                make_float2(acc[mf][nf][2]+b.x, acc[mf][nf][3]+b.y);
        }
}

// ---------------------------------------------------------------------------
extern "C" void kernel_launch(void* const* d_in, const int* in_sizes, int n_in,
                              void* d_out, int out_size)
{
    (void)in_sizes; (void)n_in; (void)out_size;
    const float* q   = (const float*)d_in[0];
    const float* k   = (const float*)d_in[1];
    const float* v   = (const float*)d_in[2];
    const float* Wq  = (const float*)d_in[3];
    const float* Wk  = (const float*)d_in[4];
    const float* Wv  = (const float*)d_in[5];
    const float* Wfc = (const float*)d_in[6];
    const float* bfc = (const float*)d_in[7];
    float* out = (float*)d_out;

    static int smem_set = 0;
    if (!smem_set){
        cudaFuncSetAttribute(attn_k, cudaFuncAttributeMaxDynamicSharedMemorySize, SMEM_ATT);
        cudaFuncSetAttribute(proj_k, cudaFuncAttributeMaxDynamicSharedMemorySize, PJ_BYTES);
        cudaFuncSetAttribute(fc_k,   cudaFuncAttributeMaxDynamicSharedMemorySize, FC_BYTES);
        smem_set = 1;
    }

    wsplit_k<<<256, 256>>>(Wfc);
    proj_k<<<dim3(256,3), 256, PJ_BYTES>>>(q, k, v, Wq, Wk, Wv);
    attn_k<<<dim3(SEQ/BQ, NG), 256, SMEM_ATT>>>();
    fc_k  <<<dim3(4,32), 256, FC_BYTES>>>(bfc, out);
}

// round 15
// speedup vs baseline: 1.5194x; 1.5194x over previous
#include <cuda_runtime.h>
#include <cstdint>
#include <math.h>

#define SEQ   2048
#define NG    16            // B*H "heads" after the plain reshape
#define HD    64
#define EMB   512
#define QSCALE 0.1803368801111204f   // 0.125 * log2(e): folds softmax scale + exp -> exp2

#define BQ 256              // q rows per CTA (8 warps x 32 rows)
#define BK 64               // keys per tile
#define NKT (SEQ/BK)        // 32 key tiles
#define PITCH 72            // smem row pitch in bf16 elems (144B: conflict-free frags)
#define PITCHB 144u

// ---- scratch (pre-split bf16 hi + residual-lo pairs) ----
__device__ __align__(16) uint16_t g_Qh [NG*SEQ*HD];
__device__ __align__(16) uint16_t g_Ql [NG*SEQ*HD];
__device__ __align__(16) uint16_t g_Kh [NG*SEQ*HD];
__device__ __align__(16) uint16_t g_Kl [NG*SEQ*HD];
__device__ __align__(16) uint16_t g_Vth[NG*HD*SEQ];   // [g][d][s]
__device__ __align__(16) uint16_t g_Vtl[NG*HD*SEQ];
__device__ __align__(16) uint16_t g_Ah [NG*SEQ*HD];   // attention out, flat [4096][512]
__device__ __align__(16) uint16_t g_Al [NG*SEQ*HD];
__device__ __align__(16) uint16_t g_Wh [EMB*EMB];
__device__ __align__(16) uint16_t g_Wl [EMB*EMB];

// ---- helpers ----
__device__ __forceinline__ void split2(float x0, float x1, uint32_t& h, uint32_t& l){
    asm("cvt.rn.bf16x2.f32 %0, %1, %2;" : "=r"(h) : "f"(x1), "f"(x0));
    float h0 = __uint_as_float(h << 16);
    float h1 = __uint_as_float(h & 0xffff0000u);
    float l0 = x0 - h0, l1 = x1 - h1;
    asm("cvt.rn.bf16x2.f32 %0, %1, %2;" : "=r"(l) : "f"(l1), "f"(l0));
}
__device__ __forceinline__ void mma_bf16(float* d, const uint32_t* a, const uint32_t* b){
    asm volatile("mma.sync.aligned.m16n8k16.row.col.f32.bf16.bf16.f32 "
        "{%0,%1,%2,%3}, {%4,%5,%6,%7}, {%8,%9}, {%0,%1,%2,%3};"
        : "+f"(d[0]), "+f"(d[1]), "+f"(d[2]), "+f"(d[3])
        : "r"(a[0]), "r"(a[1]), "r"(a[2]), "r"(a[3]), "r"(b[0]), "r"(b[1]));
}
__device__ __forceinline__ float ex2(float x){
    float r; asm("ex2.approx.f32 %0, %1;" : "=f"(r) : "f"(x)); return r;
}
__device__ __forceinline__ uint32_t smem_u32(const void* p){
    uint32_t a;
    asm("{ .reg .u64 t; cvta.to.shared.u64 t, %1; cvt.u32.u64 %0, t; }" : "=r"(a) : "l"(p));
    return a;
}
#define LDSM4(r, a) \
    asm volatile("ldmatrix.sync.aligned.m8n8.x4.shared.b16 {%0,%1,%2,%3}, [%4];" \
        : "=r"((r)[0]), "=r"((r)[1]), "=r"((r)[2]), "=r"((r)[3]) : "r"(a))
__device__ __forceinline__ void cp16(uint32_t dst, const void* src){
    asm volatile("cp.async.cg.shared.global [%0], [%1], 16;" :: "r"(dst), "l"(src));
}
#define CP_COMMIT() asm volatile("cp.async.commit_group;" ::: "memory")
#define CP_WAIT(n)  asm volatile("cp.async.wait_group %0;" :: "n"(n) : "memory")

// scalar-LDS frag loads (proj)
__device__ __forceinline__ void lda(uint32_t* a, const char* base, uint32_t off){
    a[0] = *(const uint32_t*)(base + off);
    a[1] = *(const uint32_t*)(base + off + PITCH*16u);
    a[2] = *(const uint32_t*)(base + off + 16u);
    a[3] = *(const uint32_t*)(base + off + PITCH*16u + 16u);
}
__device__ __forceinline__ void ldb(uint32_t* b, const char* base, uint32_t off){
    b[0] = *(const uint32_t*)(base + off);
    b[1] = *(const uint32_t*)(base + off + 16u);
}

// attn smem: QH[256x144] QL | K/V double buffer
#define QH_O 0u
#define QL_O 36864u
#define KV_O 73728u
#define KVB  36864u        // per buffer: KH 0 | KL 9216 | VH 18432 | VL 27648
#define SMEM_ATT 147456u

// proj smem
#define PJ_XH 0u
#define PJ_XL 18432u
#define PJ_WH 36864u
#define PJ_WL 46080u
#define PJ_BYTES 55296u     // staging tile 128x65 f32 = 33280 fits

// fc smem: double-buffered chunk: AH 18432 | AL 18432 | BH 9216 | BL 9216 = 55296/buf
#define FC_AH 0u
#define FC_AL 18432u
#define FC_BH 36864u
#define FC_BL 46080u
#define FC_BUF 55296u
#define FC_BYTES 110592u

// ---------------------------------------------------------------------------
__global__ void wsplit_k(const float* __restrict__ W)
{
    int i = (blockIdx.x*256 + threadIdx.x)*4;
    float4 x = *(const float4*)&W[i];
    uint32_t h0,l0,h1,l1;
    split2(x.x, x.y, h0, l0); split2(x.z, x.w, h1, l1);
    *(uint2*)&((uint32_t*)g_Wh)[i>>1] = make_uint2(h0,h1);
    *(uint2*)&((uint32_t*)g_Wl)[i>>1] = make_uint2(l0,l1);
}

// ---------------------------------------------------------------------------
// QKV projection via mma. ALL outputs staged through smem f32 tile and stored
// with coalesced 16B writes (Q/K natural rows, V transposed rows).
// ---------------------------------------------------------------------------
__global__ __launch_bounds__(256) void proj_k(
    const float* __restrict__ q, const float* __restrict__ k, const float* __restrict__ v,
    const float* __restrict__ Wq, const float* __restrict__ Wk, const float* __restrict__ Wv)
{
    extern __shared__ __align__(16) char smem[];
    const int t    = threadIdx.x;
    const int lane = t & 31, wid = t >> 5;
    const int r4 = lane >> 2, c2 = lane & 3;
    const int m0 = (wid >> 1) * 32;
    const int n0 = (wid & 1) * 32;
    const int which = blockIdx.y;
    const float* X = which==0 ? q  : (which==1 ? k  : v);
    const float* W = which==0 ? Wq : (which==1 ? Wk : Wv);
    const size_t rb = (size_t)blockIdx.x * 128;

    {
        const int row = t >> 1, cg = (t & 1) * 32;
        const float* src = X + (rb + row)*HD + cg;
        #pragma unroll
        for (int j=0;j<8;j++){
            float4 x = *(const float4*)&src[j*4];
            uint32_t h0,l0,h1,l1;
            split2(x.x, x.y, h0, l0); split2(x.z, x.w, h1, l1);
            uint32_t off = (uint32_t)(row*PITCH + cg + j*4)*2u;
            *(uint2*)(smem + PJ_XH + off) = make_uint2(h0,h1);
            *(uint2*)(smem + PJ_XL + off) = make_uint2(l0,l1);
        }
    }
    {
        const int row = t >> 2, cg = (t & 3) * 16;
        const float* src = W + row*HD + cg;
        #pragma unroll
        for (int j=0;j<4;j++){
            float4 x = *(const float4*)&src[j*4];
            uint32_t h0,l0,h1,l1;
            split2(x.x, x.y, h0, l0); split2(x.z, x.w, h1, l1);
            uint32_t off = (uint32_t)(row*PITCH + cg + j*4)*2u;
            *(uint2*)(smem + PJ_WH + off) = make_uint2(h0,h1);
            *(uint2*)(smem + PJ_WL + off) = make_uint2(l0,l1);
        }
    }
    __syncthreads();

    float acc[2][4][4] = {};
    #pragma unroll
    for (int ksz=0; ksz<4; ksz++){
        const int kc = ksz*16;
        uint32_t ah[2][4], al[2][4], bh[4][2], bl[4][2];
        #pragma unroll
        for (int mf=0; mf<2; mf++){
            uint32_t off = (uint32_t)((m0+16*mf+r4)*PITCH + kc + 2*c2)*2u;
            lda(ah[mf], smem + PJ_XH, off);
            lda(al[mf], smem + PJ_XL, off);
        }
        #pragma unroll
        for (int nf=0; nf<4; nf++){
            uint32_t off = (uint32_t)((n0+8*nf+r4)*PITCH + kc + 2*c2)*2u;
            ldb(bh[nf], smem + PJ_WH, off);
            ldb(bl[nf], smem + PJ_WL, off);
        }
        #pragma unroll
        for (int mf=0; mf<2; mf++)
            #pragma unroll
            for (int nf=0; nf<4; nf++){
                mma_bf16(acc[mf][nf], ah[mf], bh[nf]);
                mma_bf16(acc[mf][nf], ah[mf], bl[nf]);
                mma_bf16(acc[mf][nf], al[mf], bh[nf]);
            }
    }

    // ---- stage result tile in smem f32 [128][65] (panels dead after sync) ----
    __syncthreads();
    float* tile = (float*)smem;
    #pragma unroll
    for (int mf=0; mf<2; mf++)
        #pragma unroll
        for (int nf=0; nf<4; nf++){
            int rl = m0 + 16*mf + r4;
            int col = n0 + 8*nf + 2*c2;
            tile[rl*65 + col]       = acc[mf][nf][0];
            tile[rl*65 + col+1]     = acc[mf][nf][1];
            tile[(rl+8)*65 + col]   = acc[mf][nf][2];
            tile[(rl+8)*65 + col+1] = acc[mf][nf][3];
        }
    __syncthreads();

    if (which == 2){
        // V: transposed coalesced store into g_Vth/g_Vtl [g][d][s]
        const int g  = (int)(rb >> 11);
        const int s0 = (int)(rb & 2047);
        const int d  = t >> 2, sq = (t & 3) * 32;
        const size_t base = ((size_t)g*HD + d)*SEQ + s0 + sq;
        #pragma unroll
        for (int j8=0; j8<4; j8++){
            float f[8];
            #pragma unroll
            for (int i=0;i<8;i++) f[i] = tile[(sq + j8*8 + i)*65 + d];
            uint32_t h[4], l[4];
            split2(f[0],f[1],h[0],l[0]); split2(f[2],f[3],h[1],l[1]);
            split2(f[4],f[5],h[2],l[2]); split2(f[6],f[7],h[3],l[3]);
            *(uint4*)&((uint32_t*)g_Vth)[(base + j8*8)>>1] = make_uint4(h[0],h[1],h[2],h[3]);
            *(uint4*)&((uint32_t*)g_Vtl)[(base + j8*8)>>1] = make_uint4(l[0],l[1],l[2],l[3]);
        }
    } else {
        // Q/K: natural coalesced store (half row = 32 cols per thread)
        uint32_t* dh = (uint32_t*)(which==0 ? g_Qh : g_Kh);
        uint32_t* dl = (uint32_t*)(which==0 ? g_Ql : g_Kl);
        const float sc = (which==0) ? QSCALE : 1.0f;
        const int row = t >> 1, cg = (t & 1) * 32;
        const size_t base = ((rb + row)*HD + cg) >> 1;   // uint32 units
        const float* trow = tile + row*65 + cg;
        #pragma unroll
        for (int j8=0; j8<4; j8++){
            float f[8];
            #pragma unroll
            for (int i=0;i<8;i++) f[i] = trow[j8*8 + i]*sc;
            uint32_t h[4], l[4];
            split2(f[0],f[1],h[0],l[0]); split2(f[2],f[3],h[1],l[1]);
            split2(f[4],f[5],h[2],l[2]); split2(f[6],f[7],h[3],l[3]);
            *(uint4*)&dh[base + j8*4] = make_uint4(h[0],h[1],h[2],h[3]);
            *(uint4*)&dl[base + j8*4] = make_uint4(l[0],l[1],l[2],l[3]);
        }
    }
}

// ---------------------------------------------------------------------------
// Flash attention (exact R10 version — best measured): 8 warps x 32 q-rows,
// register P, cp.async double-buffered K/V, K/V frags shared across
// row-groups. grid = (8, 16), 256 threads, 1 CTA/SM.
// ---------------------------------------------------------------------------
__global__ __launch_bounds__(256, 1) void attn_k()
{
    extern __shared__ __align__(16) char smem[];
    const uint32_t sb = smem_u32(smem);
    const int t    = threadIdx.x;
    const int lane = t & 31, wid = t >> 5;
    const int r4 = lane >> 2, c2 = lane & 3;
    const int m0 = wid * 32;
    const int g  = blockIdx.y;
    const int q0 = blockIdx.x * BQ;

    const uint32_t a_off0 = (uint32_t)(m0 + (lane & 15)) * PITCHB + ((lane & 16) ? 16u : 0u);
    const uint32_t a_off1 = a_off0 + 16u*PITCHB;
    const uint32_t b_off  = (uint32_t)((lane & 7) + ((lane & 16) ? 8 : 0)) * PITCHB
                          + ((lane & 8) ? 16u : 0u);

    // per-thread cp.async coordinates for K/V tiles
    const int krow = t >> 2, kc = (t & 3) * 16;
    const uint32_t dko = (uint32_t)(krow*PITCH + kc)*2u;

    // ---- issue tile 0 ----
    {
        const size_t kg = (size_t)(g*SEQ + krow)*HD + kc;
        const size_t vg = ((size_t)g*HD + krow)*SEQ + kc;
        uint32_t d = sb + KV_O + dko;
        cp16(d,            g_Kh  + kg); cp16(d + 16u,          g_Kh  + kg + 8);
        cp16(d + 9216u,    g_Kl  + kg); cp16(d + 9216u + 16u,  g_Kl  + kg + 8);
        cp16(d + 18432u,   g_Vth + vg); cp16(d + 18432u + 16u, g_Vth + vg + 8);
        cp16(d + 27648u,   g_Vtl + vg); cp16(d + 27648u + 16u, g_Vtl + vg + 8);
        CP_COMMIT();
    }

    // ---- load Q tile (256 rows, one FULL 128B row per thread) ----
    {
        const uint16_t* qh = g_Qh + ((size_t)(g*SEQ + q0 + t))*HD;
        const uint16_t* ql = g_Ql + ((size_t)(g*SEQ + q0 + t))*HD;
        uint32_t off = (uint32_t)t * PITCHB;
        #pragma unroll
        for (int j=0;j<8;j++){
            *(uint4*)(smem + QH_O + off + j*16u) = *(const uint4*)(qh + j*8);
            *(uint4*)(smem + QL_O + off + j*16u) = *(const uint4*)(ql + j*8);
        }
    }

    float oacc[2][8][4] = {};
    float ls[2][2] = {};

    for (int kt = 0; kt < NKT; kt++){
        // issue next tile into the other buffer
        if (kt + 1 < NKT){
            const size_t kg = (size_t)(g*SEQ + (kt+1)*BK + krow)*HD + kc;
            const size_t vg = ((size_t)g*HD + krow)*SEQ + (kt+1)*BK + kc;
            uint32_t d = sb + KV_O + ((kt+1)&1)*KVB + dko;
            cp16(d,            g_Kh  + kg); cp16(d + 16u,          g_Kh  + kg + 8);
            cp16(d + 9216u,    g_Kl  + kg); cp16(d + 9216u + 16u,  g_Kl  + kg + 8);
            cp16(d + 18432u,   g_Vth + vg); cp16(d + 18432u + 16u, g_Vth + vg + 8);
            cp16(d + 27648u,   g_Vtl + vg); cp16(d + 27648u + 16u, g_Vtl + vg + 8);
            CP_COMMIT();
            CP_WAIT(1);
        } else {
            CP_WAIT(0);
        }
        __syncthreads();   // tile kt visible (and Q on first iter)

        const uint32_t kvb = sb + KV_O + (kt&1)*KVB;

        // ---- S = Q K^T: K frags loaded once, feed both row groups ----
        float sacc[2][8][4] = {};
        #pragma unroll
        for (int ksz=0; ksz<4; ksz++){
            const uint32_t kb = (uint32_t)ksz * 32u;
            uint32_t qh0[4], ql0[4], qh1[4], ql1[4];
            LDSM4(qh0, sb + QH_O + a_off0 + kb);
            LDSM4(ql0, sb + QL_O + a_off0 + kb);
            LDSM4(qh1, sb + QH_O + a_off1 + kb);
            LDSM4(ql1, sb + QL_O + a_off1 + kb);
            #pragma unroll
            for (int np=0; np<4; np++){
                uint32_t bh[4], bl[4];
                LDSM4(bh, kvb + (uint32_t)np*2304u + b_off + kb);
                LDSM4(bl, kvb + 9216u + (uint32_t)np*2304u + b_off + kb);
                mma_bf16(sacc[0][2*np  ], qh0, bh);
                mma_bf16(sacc[0][2*np  ], qh0, bl);
                mma_bf16(sacc[0][2*np  ], ql0, bh);
                mma_bf16(sacc[0][2*np+1], qh0, bh+2);
                mma_bf16(sacc[0][2*np+1], qh0, bl+2);
                mma_bf16(sacc[0][2*np+1], ql0, bh+2);
                mma_bf16(sacc[1][2*np  ], qh1, bh);
                mma_bf16(sacc[1][2*np  ], qh1, bl);
                mma_bf16(sacc[1][2*np  ], ql1, bh);
                mma_bf16(sacc[1][2*np+1], qh1, bh+2);
                mma_bf16(sacc[1][2*np+1], qh1, bl+2);
                mma_bf16(sacc[1][2*np+1], ql1, bh+2);
            }
        }

        // ---- fused softmax + PV per 16-key chunk ----
        #pragma unroll
        for (int ks2=0; ks2<4; ks2++){
            uint32_t pah[2][4], pal[2][4];
            #pragma unroll
            for (int mg=0; mg<2; mg++){
                #pragma unroll
                for (int j=0;j<2;j++){
                    const int nf = 2*ks2 + j;
                    float p0 = ex2(sacc[mg][nf][0]), p1 = ex2(sacc[mg][nf][1]);
                    float p2 = ex2(sacc[mg][nf][2]), p3 = ex2(sacc[mg][nf][3]);
                    ls[mg][0] += p0 + p1;
                    ls[mg][1] += p2 + p3;
                    split2(p0, p1, pah[mg][2*j  ], pal[mg][2*j  ]);
                    split2(p2, p3, pah[mg][2*j+1], pal[mg][2*j+1]);
                }
            }
            const uint32_t kb = (uint32_t)ks2 * 32u;
            #pragma unroll
            for (int np=0; np<4; np++){
                uint32_t bh[4], bl[4];
                LDSM4(bh, kvb + 18432u + (uint32_t)np*2304u + b_off + kb);
                LDSM4(bl, kvb + 27648u + (uint32_t)np*2304u + b_off + kb);
                #pragma unroll
                for (int mg=0; mg<2; mg++){
                    mma_bf16(oacc[mg][2*np  ], pah[mg], bh);
                    mma_bf16(oacc[mg][2*np  ], pah[mg], bl);
                    mma_bf16(oacc[mg][2*np  ], pal[mg], bh);
                    mma_bf16(oacc[mg][2*np+1], pah[mg], bh+2);
                    mma_bf16(oacc[mg][2*np+1], pah[mg], bl+2);
                    mma_bf16(oacc[mg][2*np+1], pal[mg], bh+2);
                }
            }
        }
        __syncthreads();   // buf[kt&1] reads done -> next iter may refill it
    }

    // ---- row sums over c2 lanes ----
    #pragma unroll
    for (int mg=0; mg<2; mg++)
        #pragma unroll
        for (int i=0;i<2;i++){
            ls[mg][i] += __shfl_xor_sync(0xffffffffu, ls[mg][i], 1);
            ls[mg][i] += __shfl_xor_sync(0xffffffffu, ls[mg][i], 2);
        }

    // ---- write O / lsum, pre-split for fc ----
    uint32_t* ah32 = (uint32_t*)g_Ah;
    uint32_t* al32 = (uint32_t*)g_Al;
    #pragma unroll
    for (int mg=0; mg<2; mg++){
        const int row = q0 + m0 + mg*16 + r4;
        const float inv0 = 1.0f / ls[mg][0], inv1 = 1.0f / ls[mg][1];
        #pragma unroll
        for (int nf=0; nf<8; nf++){
            int col = 8*nf + 2*c2;
            uint32_t h, l;
            split2(oacc[mg][nf][0]*inv0, oacc[mg][nf][1]*inv0, h, l);
            size_t idx = (((size_t)(g*SEQ + row))*HD + col) >> 1;
            ah32[idx] = h; al32[idx] = l;
            split2(oacc[mg][nf][2]*inv1, oacc[mg][nf][3]*inv1, h, l);
            idx = (((size_t)(g*SEQ + row + 8))*HD + col) >> 1;
            ah32[idx] = h; al32[idx] = l;
        }
    }
}

// ---------------------------------------------------------------------------
// FC (exact R12 version — best measured): mma + ldmatrix + cp.async double
// buffering. grid = (8, 32) = 256 CTAs, tile 128x64, 8 warps, warp 32x32.
// ---------------------------------------------------------------------------
__global__ __launch_bounds__(256) void fc_k(const float* __restrict__ bfc,
                                            float* __restrict__ out)
{
    extern __shared__ __align__(16) char smem[];
    const uint32_t sb = smem_u32(smem);
    const int t    = threadIdx.x;
    const int lane = t & 31, wid = t >> 5;
    const int r4 = lane >> 2, c2 = lane & 3;
    const int m0 = (wid >> 1) * 32;
    const int n0 = (wid & 1) * 32;
    const int eb = blockIdx.x * 64;
    const size_t rb = (size_t)blockIdx.y * 128;

    const uint32_t a_off0 = (uint32_t)(m0 + (lane & 15)) * PITCHB + ((lane & 16) ? 16u : 0u);
    const uint32_t a_off1 = a_off0 + 16u*PITCHB;
    const uint32_t b_off  = (uint32_t)(n0 + (lane & 7) + ((lane & 16) ? 8 : 0)) * PITCHB
                          + ((lane & 8) ? 16u : 0u);

    // per-thread cp.async coordinates
    const int arow = t >> 1, acg = (t & 1) * 32;
    const int brow = t >> 2, bcg = (t & 3) * 16;
    const uint32_t dao = (uint32_t)(arow*PITCH + acg)*2u;
    const uint32_t dbo = (uint32_t)(brow*PITCH + bcg)*2u;

    // issue chunk 0
    {
        const uint16_t* ah = g_Ah + (rb + arow)*EMB + acg;
        const uint16_t* al = g_Al + (rb + arow)*EMB + acg;
        const uint16_t* bh = g_Wh + (size_t)(eb + brow)*EMB + bcg;
        const uint16_t* bl = g_Wl + (size_t)(eb + brow)*EMB + bcg;
        uint32_t d = sb;
        #pragma unroll
        for (int j=0;j<4;j++){
            cp16(d + FC_AH + dao + j*16u, ah + j*8);
            cp16(d + FC_AL + dao + j*16u, al + j*8);
        }
        cp16(d + FC_BH + dbo,       bh);
        cp16(d + FC_BH + dbo + 16u, bh + 8);
        cp16(d + FC_BL + dbo,       bl);
        cp16(d + FC_BL + dbo + 16u, bl + 8);
        CP_COMMIT();
    }

    float acc[2][4][4] = {};

    for (int kc2 = 0; kc2 < 8; kc2++){
        if (kc2 + 1 < 8){
            const int f1 = (kc2+1) * 64;
            const uint16_t* ah = g_Ah + (rb + arow)*EMB + f1 + acg;
            const uint16_t* al = g_Al + (rb + arow)*EMB + f1 + acg;
            const uint16_t* bh = g_Wh + (size_t)(eb + brow)*EMB + f1 + bcg;
            const uint16_t* bl = g_Wl + (size_t)(eb + brow)*EMB + f1 + bcg;
            uint32_t d = sb + ((kc2+1)&1)*FC_BUF;
            #pragma unroll
            for (int j=0;j<4;j++){
                cp16(d + FC_AH + dao + j*16u, ah + j*8);
                cp16(d + FC_AL + dao + j*16u, al + j*8);
            }
            cp16(d + FC_BH + dbo,       bh);
            cp16(d + FC_BH + dbo + 16u, bh + 8);
            cp16(d + FC_BL + dbo,       bl);
            cp16(d + FC_BL + dbo + 16u, bl + 8);
            CP_COMMIT();
            CP_WAIT(1);
        } else {
            CP_WAIT(0);
        }
        __syncthreads();   // chunk kc2 visible

        const uint32_t buf = sb + (kc2&1)*FC_BUF;

        #pragma unroll
        for (int ksz=0; ksz<4; ksz++){
            const uint32_t kb = (uint32_t)ksz * 32u;
            uint32_t ah0[4], al0[4], ah1[4], al1[4], bh[4], bl[4];
            LDSM4(ah0, buf + FC_AH + a_off0 + kb);
            LDSM4(al0, buf + FC_AL + a_off0 + kb);
            LDSM4(ah1, buf + FC_AH + a_off1 + kb);
            LDSM4(al1, buf + FC_AL + a_off1 + kb);
            LDSM4(bh,  buf + FC_BH + b_off + kb);
            LDSM4(bl,  buf + FC_BL + b_off + kb);
            uint32_t bh2[4], bl2[4];
            LDSM4(bh2, buf + FC_BH + 16u*PITCHB + b_off + kb);
            LDSM4(bl2, buf + FC_BL + 16u*PITCHB + b_off + kb);

            mma_bf16(acc[0][0], ah0, bh);   mma_bf16(acc[0][0], ah0, bl);   mma_bf16(acc[0][0], al0, bh);
            mma_bf16(acc[0][1], ah0, bh+2); mma_bf16(acc[0][1], ah0, bl+2); mma_bf16(acc[0][1], al0, bh+2);
            mma_bf16(acc[0][2], ah0, bh2);  mma_bf16(acc[0][2], ah0, bl2);  mma_bf16(acc[0][2], al0, bh2);
            mma_bf16(acc[0][3], ah0, bh2+2);mma_bf16(acc[0][3], ah0, bl2+2);mma_bf16(acc[0][3], al0, bh2+2);
            mma_bf16(acc[1][0], ah1, bh);   mma_bf16(acc[1][0], ah1, bl);   mma_bf16(acc[1][0], al1, bh);
            mma_bf16(acc[1][1], ah1, bh+2); mma_bf16(acc[1][1], ah1, bl+2); mma_bf16(acc[1][1], al1, bh+2);
            mma_bf16(acc[1][2], ah1, bh2);  mma_bf16(acc[1][2], ah1, bl2);  mma_bf16(acc[1][2], al1, bh2);
            mma_bf16(acc[1][3], ah1, bh2+2);mma_bf16(acc[1][3], ah1, bl2+2);mma_bf16(acc[1][3], al1, bh2+2);
        }
        __syncthreads();   // buf reads done -> next iter may refill it
    }

    #pragma unroll
    for (int mf=0; mf<2; mf++)
        #pragma unroll
        for (int nf=0; nf<4; nf++){
            int row = (int)rb + m0 + 16*mf + r4;
            int col = eb + n0 + 8*nf + 2*c2;
            float2 b = *(const float2*)&bfc[col];
            *(float2*)&out[(size_t)row*EMB + col] =
                make_float2(acc[mf][nf][0]+b.x, acc[mf][nf][1]+b.y);
            *(float2*)&out[(size_t)(row+8)*EMB + col] =
                make_float2(acc[mf][nf][2]+b.x, acc[mf][nf][3]+b.y);
        }
}

// ---------------------------------------------------------------------------
extern "C" void kernel_launch(void* const* d_in, const int* in_sizes, int n_in,
                              void* d_out, int out_size)
{
    (void)in_sizes; (void)n_in; (void)out_size;
    const float* q   = (const float*)d_in[0];
    const float* k   = (const float*)d_in[1];
    const float* v   = (const float*)d_in[2];
    const float* Wq  = (const float*)d_in[3];
    const float* Wk  = (const float*)d_in[4];
    const float* Wv  = (const float*)d_in[5];
    const float* Wfc = (const float*)d_in[6];
    const float* bfc = (const float*)d_in[7];
    float* out = (float*)d_out;

    static int smem_set = 0;
    if (!smem_set){
        cudaFuncSetAttribute(attn_k, cudaFuncAttributeMaxDynamicSharedMemorySize, SMEM_ATT);
        cudaFuncSetAttribute(proj_k, cudaFuncAttributeMaxDynamicSharedMemorySize, PJ_BYTES);
        cudaFuncSetAttribute(fc_k,   cudaFuncAttributeMaxDynamicSharedMemorySize, FC_BYTES);
        smem_set = 1;
    }

    wsplit_k<<<256, 256>>>(Wfc);
    proj_k<<<dim3(256,3), 256, PJ_BYTES>>>(q, k, v, Wq, Wk, Wv);
    attn_k<<<dim3(SEQ/BQ, NG), 256, SMEM_ATT>>>();
    fc_k  <<<dim3(8,32), 256, FC_BYTES>>>(bfc, out);
}

// round 16
// speedup vs baseline: 1.5817x; 1.0410x over previous
#include <cuda_runtime.h>
#include <cstdint>
#include <math.h>

#define SEQ   2048
#define NG    16            // B*H "heads" after the plain reshape
#define HD    64
#define EMB   512
#define QSCALE 0.1803368801111204f   // 0.125 * log2(e): folds softmax scale + exp -> exp2

#define BQ 256              // q rows per CTA (8 warps x 32 rows)
#define BK 64               // keys per tile
#define NKT (SEQ/BK)        // 32 key tiles
#define PITCH 72            // smem row pitch in bf16 elems (144B: conflict-free frags)
#define PITCHB 144u

// ---- scratch (pre-split bf16 hi + residual-lo pairs) ----
__device__ __align__(16) uint16_t g_Qh [NG*SEQ*HD];
__device__ __align__(16) uint16_t g_Ql [NG*SEQ*HD];
__device__ __align__(16) uint16_t g_Kh [NG*SEQ*HD];
__device__ __align__(16) uint16_t g_Kl [NG*SEQ*HD];
__device__ __align__(16) uint16_t g_Vth[NG*HD*SEQ];   // [g][d][s]
__device__ __align__(16) uint16_t g_Vtl[NG*HD*SEQ];
__device__ __align__(16) uint16_t g_Ah [NG*SEQ*HD];   // attention out, flat [4096][512]
__device__ __align__(16) uint16_t g_Al [NG*SEQ*HD];
__device__ __align__(16) uint16_t g_Wh [EMB*EMB];
__device__ __align__(16) uint16_t g_Wl [EMB*EMB];

// ---- helpers ----
__device__ __forceinline__ void split2(float x0, float x1, uint32_t& h, uint32_t& l){
    asm("cvt.rn.bf16x2.f32 %0, %1, %2;" : "=r"(h) : "f"(x1), "f"(x0));
    float h0 = __uint_as_float(h << 16);
    float h1 = __uint_as_float(h & 0xffff0000u);
    float l0 = x0 - h0, l1 = x1 - h1;
    asm("cvt.rn.bf16x2.f32 %0, %1, %2;" : "=r"(l) : "f"(l1), "f"(l0));
}
__device__ __forceinline__ void mma_bf16(float* d, const uint32_t* a, const uint32_t* b){
    asm volatile("mma.sync.aligned.m16n8k16.row.col.f32.bf16.bf16.f32 "
        "{%0,%1,%2,%3}, {%4,%5,%6,%7}, {%8,%9}, {%0,%1,%2,%3};"
        : "+f"(d[0]), "+f"(d[1]), "+f"(d[2]), "+f"(d[3])
        : "r"(a[0]), "r"(a[1]), "r"(a[2]), "r"(a[3]), "r"(b[0]), "r"(b[1]));
}
__device__ __forceinline__ float ex2(float x){
    float r; asm("ex2.approx.f32 %0, %1;" : "=f"(r) : "f"(x)); return r;
}
__device__ __forceinline__ uint32_t smem_u32(const void* p){
    uint32_t a;
    asm("{ .reg .u64 t; cvta.to.shared.u64 t, %1; cvt.u32.u64 %0, t; }" : "=r"(a) : "l"(p));
    return a;
}
#define LDSM4(r, a) \
    asm volatile("ldmatrix.sync.aligned.m8n8.x4.shared.b16 {%0,%1,%2,%3}, [%4];" \
        : "=r"((r)[0]), "=r"((r)[1]), "=r"((r)[2]), "=r"((r)[3]) : "r"(a))
__device__ __forceinline__ void cp16(uint32_t dst, const void* src){
    asm volatile("cp.async.cg.shared.global [%0], [%1], 16;" :: "r"(dst), "l"(src));
}
#define CP_COMMIT() asm volatile("cp.async.commit_group;" ::: "memory")
#define CP_WAIT(n)  asm volatile("cp.async.wait_group %0;" :: "n"(n) : "memory")

// scalar-LDS frag loads (proj)
__device__ __forceinline__ void lda(uint32_t* a, const char* base, uint32_t off){
    a[0] = *(const uint32_t*)(base + off);
    a[1] = *(const uint32_t*)(base + off + PITCH*16u);
    a[2] = *(const uint32_t*)(base + off + 16u);
    a[3] = *(const uint32_t*)(base + off + PITCH*16u + 16u);
}
__device__ __forceinline__ void ldb(uint32_t* b, const char* base, uint32_t off){
    b[0] = *(const uint32_t*)(base + off);
    b[1] = *(const uint32_t*)(base + off + 16u);
}

// attn smem: QH[256x144] QL | K/V double buffer
#define QH_O 0u
#define QL_O 36864u
#define KV_O 73728u
#define KVB  36864u        // per buffer: KH 0 | KL 9216 | VH 18432 | VL 27648
#define SMEM_ATT 147456u

// proj smem
#define PJ_XH 0u
#define PJ_XL 18432u
#define PJ_WH 36864u
#define PJ_WL 46080u
#define PJ_BYTES 55296u     // staging tile 128x65 f32 = 33280 fits

// fc smem (128x128 tile, 512 thr): per buffer AH 0 | AL 18432 | BH 36864 | BL 55296
#define FC_AH 0u
#define FC_AL 18432u
#define FC_BH 36864u
#define FC_BL 55296u
#define FC_BUF 73728u
#define FC_BYTES 147456u

// ---------------------------------------------------------------------------
// QKV projection via mma + fused Wfc split (blockIdx.y == 3).
// Outputs staged through smem f32 tile, stored with coalesced 16B writes.
// ---------------------------------------------------------------------------
__global__ __launch_bounds__(256) void proj_k(
    const float* __restrict__ q, const float* __restrict__ k, const float* __restrict__ v,
    const float* __restrict__ Wq, const float* __restrict__ Wk, const float* __restrict__ Wv,
    const float* __restrict__ Wfc)
{
    extern __shared__ __align__(16) char smem[];
    const int which = blockIdx.y;
    const int t = threadIdx.x;

    if (which == 3){   // Wfc -> split bf16 (fused prep; 256 CTAs x 256 thr x 4 elems)
        int i = (blockIdx.x*256 + t)*4;
        float4 x = *(const float4*)&Wfc[i];
        uint32_t h0,l0,h1,l1;
        split2(x.x, x.y, h0, l0); split2(x.z, x.w, h1, l1);
        *(uint2*)&((uint32_t*)g_Wh)[i>>1] = make_uint2(h0,h1);
        *(uint2*)&((uint32_t*)g_Wl)[i>>1] = make_uint2(l0,l1);
        return;
    }

    const int lane = t & 31, wid = t >> 5;
    const int r4 = lane >> 2, c2 = lane & 3;
    const int m0 = (wid >> 1) * 32;
    const int n0 = (wid & 1) * 32;
    const float* X = which==0 ? q  : (which==1 ? k  : v);
    const float* W = which==0 ? Wq : (which==1 ? Wk : Wv);
    const size_t rb = (size_t)blockIdx.x * 128;

    {
        const int row = t >> 1, cg = (t & 1) * 32;
        const float* src = X + (rb + row)*HD + cg;
        #pragma unroll
        for (int j=0;j<8;j++){
            float4 x = *(const float4*)&src[j*4];
            uint32_t h0,l0,h1,l1;
            split2(x.x, x.y, h0, l0); split2(x.z, x.w, h1, l1);
            uint32_t off = (uint32_t)(row*PITCH + cg + j*4)*2u;
            *(uint2*)(smem + PJ_XH + off) = make_uint2(h0,h1);
            *(uint2*)(smem + PJ_XL + off) = make_uint2(l0,l1);
        }
    }
    {
        const int row = t >> 2, cg = (t & 3) * 16;
        const float* src = W + row*HD + cg;
        #pragma unroll
        for (int j=0;j<4;j++){
            float4 x = *(const float4*)&src[j*4];
            uint32_t h0,l0,h1,l1;
            split2(x.x, x.y, h0, l0); split2(x.z, x.w, h1, l1);
            uint32_t off = (uint32_t)(row*PITCH + cg + j*4)*2u;
            *(uint2*)(smem + PJ_WH + off) = make_uint2(h0,h1);
            *(uint2*)(smem + PJ_WL + off) = make_uint2(l0,l1);
        }
    }
    __syncthreads();

    float acc[2][4][4] = {};
    #pragma unroll
    for (int ksz=0; ksz<4; ksz++){
        const int kc = ksz*16;
        uint32_t ah[2][4], al[2][4], bh[4][2], bl[4][2];
        #pragma unroll
        for (int mf=0; mf<2; mf++){
            uint32_t off = (uint32_t)((m0+16*mf+r4)*PITCH + kc + 2*c2)*2u;
            lda(ah[mf], smem + PJ_XH, off);
            lda(al[mf], smem + PJ_XL, off);
        }
        #pragma unroll
        for (int nf=0; nf<4; nf++){
            uint32_t off = (uint32_t)((n0+8*nf+r4)*PITCH + kc + 2*c2)*2u;
            ldb(bh[nf], smem + PJ_WH, off);
            ldb(bl[nf], smem + PJ_WL, off);
        }
        #pragma unroll
        for (int mf=0; mf<2; mf++)
            #pragma unroll
            for (int nf=0; nf<4; nf++){
                mma_bf16(acc[mf][nf], ah[mf], bh[nf]);
                mma_bf16(acc[mf][nf], ah[mf], bl[nf]);
                mma_bf16(acc[mf][nf], al[mf], bh[nf]);
            }
    }

    // ---- stage result tile in smem f32 [128][65] ----
    __syncthreads();
    float* tile = (float*)smem;
    #pragma unroll
    for (int mf=0; mf<2; mf++)
        #pragma unroll
        for (int nf=0; nf<4; nf++){
            int rl = m0 + 16*mf + r4;
            int col = n0 + 8*nf + 2*c2;
            tile[rl*65 + col]       = acc[mf][nf][0];
            tile[rl*65 + col+1]     = acc[mf][nf][1];
            tile[(rl+8)*65 + col]   = acc[mf][nf][2];
            tile[(rl+8)*65 + col+1] = acc[mf][nf][3];
        }
    __syncthreads();

    if (which == 2){
        const int g  = (int)(rb >> 11);
        const int s0 = (int)(rb & 2047);
        const int d  = t >> 2, sq = (t & 3) * 32;
        const size_t base = ((size_t)g*HD + d)*SEQ + s0 + sq;
        #pragma unroll
        for (int j8=0; j8<4; j8++){
            float f[8];
            #pragma unroll
            for (int i=0;i<8;i++) f[i] = tile[(sq + j8*8 + i)*65 + d];
            uint32_t h[4], l[4];
            split2(f[0],f[1],h[0],l[0]); split2(f[2],f[3],h[1],l[1]);
            split2(f[4],f[5],h[2],l[2]); split2(f[6],f[7],h[3],l[3]);
            *(uint4*)&((uint32_t*)g_Vth)[(base + j8*8)>>1] = make_uint4(h[0],h[1],h[2],h[3]);
            *(uint4*)&((uint32_t*)g_Vtl)[(base + j8*8)>>1] = make_uint4(l[0],l[1],l[2],l[3]);
        }
    } else {
        uint32_t* dh = (uint32_t*)(which==0 ? g_Qh : g_Kh);
        uint32_t* dl = (uint32_t*)(which==0 ? g_Ql : g_Kl);
        const float sc = (which==0) ? QSCALE : 1.0f;
        const int row = t >> 1, cg = (t & 1) * 32;
        const size_t base = ((rb + row)*HD + cg) >> 1;
        const float* trow = tile + row*65 + cg;
        #pragma unroll
        for (int j8=0; j8<4; j8++){
            float f[8];
            #pragma unroll
            for (int i=0;i<8;i++) f[i] = trow[j8*8 + i]*sc;
            uint32_t h[4], l[4];
            split2(f[0],f[1],h[0],l[0]); split2(f[2],f[3],h[1],l[1]);
            split2(f[4],f[5],h[2],l[2]); split2(f[6],f[7],h[3],l[3]);
            *(uint4*)&dh[base + j8*4] = make_uint4(h[0],h[1],h[2],h[3]);
            *(uint4*)&dl[base + j8*4] = make_uint4(l[0],l[1],l[2],l[3]);
        }
    }
}

// ---------------------------------------------------------------------------
// Flash attention (exact R10 version — best measured): 8 warps x 32 q-rows,
// register P, cp.async double-buffered K/V, K/V frags shared across
// row-groups. grid = (8, 16), 256 threads, 1 CTA/SM.
// ---------------------------------------------------------------------------
__global__ __launch_bounds__(256, 1) void attn_k()
{
    extern __shared__ __align__(16) char smem[];
    const uint32_t sb = smem_u32(smem);
    const int t    = threadIdx.x;
    const int lane = t & 31, wid = t >> 5;
    const int r4 = lane >> 2, c2 = lane & 3;
    const int m0 = wid * 32;
    const int g  = blockIdx.y;
    const int q0 = blockIdx.x * BQ;

    const uint32_t a_off0 = (uint32_t)(m0 + (lane & 15)) * PITCHB + ((lane & 16) ? 16u : 0u);
    const uint32_t a_off1 = a_off0 + 16u*PITCHB;
    const uint32_t b_off  = (uint32_t)((lane & 7) + ((lane & 16) ? 8 : 0)) * PITCHB
                          + ((lane & 8) ? 16u : 0u);

    const int krow = t >> 2, kc = (t & 3) * 16;
    const uint32_t dko = (uint32_t)(krow*PITCH + kc)*2u;

    // ---- issue tile 0 ----
    {
        const size_t kg = (size_t)(g*SEQ + krow)*HD + kc;
        const size_t vg = ((size_t)g*HD + krow)*SEQ + kc;
        uint32_t d = sb + KV_O + dko;
        cp16(d,            g_Kh  + kg); cp16(d + 16u,          g_Kh  + kg + 8);
        cp16(d + 9216u,    g_Kl  + kg); cp16(d + 9216u + 16u,  g_Kl  + kg + 8);
        cp16(d + 18432u,   g_Vth + vg); cp16(d + 18432u + 16u, g_Vth + vg + 8);
        cp16(d + 27648u,   g_Vtl + vg); cp16(d + 27648u + 16u, g_Vtl + vg + 8);
        CP_COMMIT();
    }

    // ---- load Q tile (256 rows, one FULL 128B row per thread) ----
    {
        const uint16_t* qh = g_Qh + ((size_t)(g*SEQ + q0 + t))*HD;
        const uint16_t* ql = g_Ql + ((size_t)(g*SEQ + q0 + t))*HD;
        uint32_t off = (uint32_t)t * PITCHB;
        #pragma unroll
        for (int j=0;j<8;j++){
            *(uint4*)(smem + QH_O + off + j*16u) = *(const uint4*)(qh + j*8);
            *(uint4*)(smem + QL_O + off + j*16u) = *(const uint4*)(ql + j*8);
        }
    }

    float oacc[2][8][4] = {};
    float ls[2][2] = {};

    for (int kt = 0; kt < NKT; kt++){
        if (kt + 1 < NKT){
            const size_t kg = (size_t)(g*SEQ + (kt+1)*BK + krow)*HD + kc;
            const size_t vg = ((size_t)g*HD + krow)*SEQ + (kt+1)*BK + kc;
            uint32_t d = sb + KV_O + ((kt+1)&1)*KVB + dko;
            cp16(d,            g_Kh  + kg); cp16(d + 16u,          g_Kh  + kg + 8);
            cp16(d + 9216u,    g_Kl  + kg); cp16(d + 9216u + 16u,  g_Kl  + kg + 8);
            cp16(d + 18432u,   g_Vth + vg); cp16(d + 18432u + 16u, g_Vth + vg + 8);
            cp16(d + 27648u,   g_Vtl + vg); cp16(d + 27648u + 16u, g_Vtl + vg + 8);
            CP_COMMIT();
            CP_WAIT(1);
        } else {
            CP_WAIT(0);
        }
        __syncthreads();

        const uint32_t kvb = sb + KV_O + (kt&1)*KVB;

        // ---- S = Q K^T ----
        float sacc[2][8][4] = {};
        #pragma unroll
        for (int ksz=0; ksz<4; ksz++){
            const uint32_t kb = (uint32_t)ksz * 32u;
            uint32_t qh0[4], ql0[4], qh1[4], ql1[4];
            LDSM4(qh0, sb + QH_O + a_off0 + kb);
            LDSM4(ql0, sb + QL_O + a_off0 + kb);
            LDSM4(qh1, sb + QH_O + a_off1 + kb);
            LDSM4(ql1, sb + QL_O + a_off1 + kb);
            #pragma unroll
            for (int np=0; np<4; np++){
                uint32_t bh[4], bl[4];
                LDSM4(bh, kvb + (uint32_t)np*2304u + b_off + kb);
                LDSM4(bl, kvb + 9216u + (uint32_t)np*2304u + b_off + kb);
                mma_bf16(sacc[0][2*np  ], qh0, bh);
                mma_bf16(sacc[0][2*np  ], qh0, bl);
                mma_bf16(sacc[0][2*np  ], ql0, bh);
                mma_bf16(sacc[0][2*np+1], qh0, bh+2);
                mma_bf16(sacc[0][2*np+1], qh0, bl+2);
                mma_bf16(sacc[0][2*np+1], ql0, bh+2);
                mma_bf16(sacc[1][2*np  ], qh1, bh);
                mma_bf16(sacc[1][2*np  ], qh1, bl);
                mma_bf16(sacc[1][2*np  ], ql1, bh);
                mma_bf16(sacc[1][2*np+1], qh1, bh+2);
                mma_bf16(sacc[1][2*np+1], qh1, bl+2);
                mma_bf16(sacc[1][2*np+1], ql1, bh+2);
            }
        }

        // ---- fused softmax + PV per 16-key chunk ----
        #pragma unroll
        for (int ks2=0; ks2<4; ks2++){
            uint32_t pah[2][4], pal[2][4];
            #pragma unroll
            for (int mg=0; mg<2; mg++){
                #pragma unroll
                for (int j=0;j<2;j++){
                    const int nf = 2*ks2 + j;
                    float p0 = ex2(sacc[mg][nf][0]), p1 = ex2(sacc[mg][nf][1]);
                    float p2 = ex2(sacc[mg][nf][2]), p3 = ex2(sacc[mg][nf][3]);
                    ls[mg][0] += p0 + p1;
                    ls[mg][1] += p2 + p3;
                    split2(p0, p1, pah[mg][2*j  ], pal[mg][2*j  ]);
                    split2(p2, p3, pah[mg][2*j+1], pal[mg][2*j+1]);
                }
            }
            const uint32_t kb = (uint32_t)ks2 * 32u;
            #pragma unroll
            for (int np=0; np<4; np++){
                uint32_t bh[4], bl[4];
                LDSM4(bh, kvb + 18432u + (uint32_t)np*2304u + b_off + kb);
                LDSM4(bl, kvb + 27648u + (uint32_t)np*2304u + b_off + kb);
                #pragma unroll
                for (int mg=0; mg<2; mg++){
                    mma_bf16(oacc[mg][2*np  ], pah[mg], bh);
                    mma_bf16(oacc[mg][2*np  ], pah[mg], bl);
                    mma_bf16(oacc[mg][2*np  ], pal[mg], bh);
                    mma_bf16(oacc[mg][2*np+1], pah[mg], bh+2);
                    mma_bf16(oacc[mg][2*np+1], pah[mg], bl+2);
                    mma_bf16(oacc[mg][2*np+1], pal[mg], bh+2);
                }
            }
        }
        __syncthreads();
    }

    // ---- row sums over c2 lanes ----
    #pragma unroll
    for (int mg=0; mg<2; mg++)
        #pragma unroll
        for (int i=0;i<2;i++){
            ls[mg][i] += __shfl_xor_sync(0xffffffffu, ls[mg][i], 1);
            ls[mg][i] += __shfl_xor_sync(0xffffffffu, ls[mg][i], 2);
        }

    // ---- write O / lsum, pre-split for fc ----
    uint32_t* ah32 = (uint32_t*)g_Ah;
    uint32_t* al32 = (uint32_t*)g_Al;
    #pragma unroll
    for (int mg=0; mg<2; mg++){
        const int row = q0 + m0 + mg*16 + r4;
        const float inv0 = 1.0f / ls[mg][0], inv1 = 1.0f / ls[mg][1];
        #pragma unroll
        for (int nf=0; nf<8; nf++){
            int col = 8*nf + 2*c2;
            uint32_t h, l;
            split2(oacc[mg][nf][0]*inv0, oacc[mg][nf][1]*inv0, h, l);
            size_t idx = (((size_t)(g*SEQ + row))*HD + col) >> 1;
            ah32[idx] = h; al32[idx] = l;
            split2(oacc[mg][nf][2]*inv1, oacc[mg][nf][3]*inv1, h, l);
            idx = (((size_t)(g*SEQ + row + 8))*HD + col) >> 1;
            ah32[idx] = h; al32[idx] = l;
        }
    }
}

// ---------------------------------------------------------------------------
// FC: 512 threads, 128x128 tiles, 16 warps (4m x 4n of 32x32), cp.async
// double-buffered. grid = (4, 32) = 128 CTAs, 1 CTA/SM (16 warps of TLP).
// ---------------------------------------------------------------------------
__global__ __launch_bounds__(512, 1) void fc_k(const float* __restrict__ bfc,
                                               float* __restrict__ out)
{
    extern __shared__ __align__(16) char smem[];
    const uint32_t sb = smem_u32(smem);
    const int t    = threadIdx.x;
    const int lane = t & 31, wid = t >> 5;
    const int r4 = lane >> 2, c2 = lane & 3;
    const int m0 = (wid >> 2) * 32;
    const int n0 = (wid & 3) * 32;
    const int eb = blockIdx.x * 128;
    const size_t rb = (size_t)blockIdx.y * 128;

    const uint32_t a_off0 = (uint32_t)(m0 + (lane & 15)) * PITCHB + ((lane & 16) ? 16u : 0u);
    const uint32_t a_off1 = a_off0 + 16u*PITCHB;
    const uint32_t b_off  = (uint32_t)(n0 + (lane & 7) + ((lane & 16) ? 8 : 0)) * PITCHB
                          + ((lane & 8) ? 16u : 0u);

    // per-thread cp.async coordinates (A and B both 128 rows x 64 k, 512 thr)
    const int arow = t >> 2, acg = (t & 3) * 16;
    const uint32_t dao = (uint32_t)(arow*PITCH + acg)*2u;

    // issue chunk 0
    {
        const uint16_t* ah = g_Ah + (rb + arow)*EMB + acg;
        const uint16_t* al = g_Al + (rb + arow)*EMB + acg;
        const uint16_t* bh = g_Wh + (size_t)(eb + arow)*EMB + acg;
        const uint16_t* bl = g_Wl + (size_t)(eb + arow)*EMB + acg;
        #pragma unroll
        for (int j=0;j<2;j++){
            cp16(sb + FC_AH + dao + j*16u, ah + j*8);
            cp16(sb + FC_AL + dao + j*16u, al + j*8);
            cp16(sb + FC_BH + dao + j*16u, bh + j*8);
            cp16(sb + FC_BL + dao + j*16u, bl + j*8);
        }
        CP_COMMIT();
    }

    float acc[2][4][4] = {};

    for (int kc2 = 0; kc2 < 8; kc2++){
        if (kc2 + 1 < 8){
            const int f1 = (kc2+1) * 64;
            const uint16_t* ah = g_Ah + (rb + arow)*EMB + f1 + acg;
            const uint16_t* al = g_Al + (rb + arow)*EMB + f1 + acg;
            const uint16_t* bh = g_Wh + (size_t)(eb + arow)*EMB + f1 + acg;
            const uint16_t* bl = g_Wl + (size_t)(eb + arow)*EMB + f1 + acg;
            uint32_t d = sb + ((kc2+1)&1)*FC_BUF;
            #pragma unroll
            for (int j=0;j<2;j++){
                cp16(d + FC_AH + dao + j*16u, ah + j*8);
                cp16(d + FC_AL + dao + j*16u, al + j*8);
                cp16(d + FC_BH + dao + j*16u, bh + j*8);
                cp16(d + FC_BL + dao + j*16u, bl + j*8);
            }
            CP_COMMIT();
            CP_WAIT(1);
        } else {
            CP_WAIT(0);
        }
        __syncthreads();   // chunk kc2 visible

        const uint32_t buf = sb + (kc2&1)*FC_BUF;

        #pragma unroll
        for (int ksz=0; ksz<4; ksz++){
            const uint32_t kb = (uint32_t)ksz * 32u;
            uint32_t ah0[4], al0[4], ah1[4], al1[4], bh[4], bl[4];
            LDSM4(ah0, buf + FC_AH + a_off0 + kb);
            LDSM4(al0, buf + FC_AL + a_off0 + kb);
            LDSM4(ah1, buf + FC_AH + a_off1 + kb);
            LDSM4(al1, buf + FC_AL + a_off1 + kb);
            LDSM4(bh,  buf + FC_BH + b_off + kb);
            LDSM4(bl,  buf + FC_BL + b_off + kb);
            uint32_t bh2[4], bl2[4];
            LDSM4(bh2, buf + FC_BH + 16u*PITCHB + b_off + kb);
            LDSM4(bl2, buf + FC_BL + 16u*PITCHB + b_off + kb);

            mma_bf16(acc[0][0], ah0, bh);   mma_bf16(acc[0][0], ah0, bl);   mma_bf16(acc[0][0], al0, bh);
            mma_bf16(acc[0][1], ah0, bh+2); mma_bf16(acc[0][1], ah0, bl+2); mma_bf16(acc[0][1], al0, bh+2);
            mma_bf16(acc[0][2], ah0, bh2);  mma_bf16(acc[0][2], ah0, bl2);  mma_bf16(acc[0][2], al0, bh2);
            mma_bf16(acc[0][3], ah0, bh2+2);mma_bf16(acc[0][3], ah0, bl2+2);mma_bf16(acc[0][3], al0, bh2+2);
            mma_bf16(acc[1][0], ah1, bh);   mma_bf16(acc[1][0], ah1, bl);   mma_bf16(acc[1][0], al1, bh);
            mma_bf16(acc[1][1], ah1, bh+2); mma_bf16(acc[1][1], ah1, bl+2); mma_bf16(acc[1][1], al1, bh+2);
            mma_bf16(acc[1][2], ah1, bh2);  mma_bf16(acc[1][2], ah1, bl2);  mma_bf16(acc[1][2], al1, bh2);
            mma_bf16(acc[1][3], ah1, bh2+2);mma_bf16(acc[1][3], ah1, bl2+2);mma_bf16(acc[1][3], al1, bh2+2);
        }
        __syncthreads();   // buf reads done -> next iter may refill it
    }

    #pragma unroll
    for (int mf=0; mf<2; mf++)
        #pragma unroll
        for (int nf=0; nf<4; nf++){
            int row = (int)rb + m0 + 16*mf + r4;
            int col = eb + n0 + 8*nf + 2*c2;
            float2 b = *(const float2*)&bfc[col];
            *(float2*)&out[(size_t)row*EMB + col] =
                make_float2(acc[mf][nf][0]+b.x, acc[mf][nf][1]+b.y);
            *(float2*)&out[(size_t)(row+8)*EMB + col] =
                make_float2(acc[mf][nf][2]+b.x, acc[mf][nf][3]+b.y);
        }
}

// ---------------------------------------------------------------------------
extern "C" void kernel_launch(void* const* d_in, const int* in_sizes, int n_in,
                              void* d_out, int out_size)
{
    (void)in_sizes; (void)n_in; (void)out_size;
    const float* q   = (const float*)d_in[0];
    const float* k   = (const float*)d_in[1];
    const float* v   = (const float*)d_in[2];
    const float* Wq  = (const float*)d_in[3];
    const float* Wk  = (const float*)d_in[4];
    const float* Wv  = (const float*)d_in[5];
    const float* Wfc = (const float*)d_in[6];
    const float* bfc = (const float*)d_in[7];
    float* out = (float*)d_out;

    static int smem_set = 0;
    if (!smem_set){
        cudaFuncSetAttribute(attn_k, cudaFuncAttributeMaxDynamicSharedMemorySize, SMEM_ATT);
        cudaFuncSetAttribute(proj_k, cudaFuncAttributeMaxDynamicSharedMemorySize, PJ_BYTES);
        cudaFuncSetAttribute(fc_k,   cudaFuncAttributeMaxDynamicSharedMemorySize, FC_BYTES);
        smem_set = 1;
    }

    proj_k<<<dim3(256,4), 256, PJ_BYTES>>>(q, k, v, Wq, Wk, Wv, Wfc);
    attn_k<<<dim3(SEQ/BQ, NG), 256, SMEM_ATT>>>();
    fc_k  <<<dim3(4,32), 512, FC_BYTES>>>(bfc, out);
}

// round 17
// speedup vs baseline: 1.6207x; 1.0246x over previous
#include <cuda_runtime.h>
#include <cstdint>
#include <math.h>

#define SEQ   2048
#define NG    16            // B*H "heads" after the plain reshape
#define HD    64
#define EMB   512
#define QSCALE 0.1803368801111204f   // 0.125 * log2(e): folds softmax scale + exp -> exp2

#define BQ 256              // q rows per CTA (8 warps x 32 rows)
#define BK 64               // keys per tile
#define NKT (SEQ/BK)        // 32 key tiles
#define PITCH 72            // smem row pitch in bf16 elems (144B: conflict-free frags)
#define PITCHB 144u

// ---- scratch (pre-split bf16 hi + residual-lo pairs) ----
__device__ __align__(16) uint16_t g_Qh [NG*SEQ*HD];
__device__ __align__(16) uint16_t g_Ql [NG*SEQ*HD];
__device__ __align__(16) uint16_t g_Kh [NG*SEQ*HD];
__device__ __align__(16) uint16_t g_Kl [NG*SEQ*HD];
__device__ __align__(16) uint16_t g_Vth[NG*HD*SEQ];   // [g][d][s]
__device__ __align__(16) uint16_t g_Vtl[NG*HD*SEQ];
__device__ __align__(16) uint16_t g_Ah [NG*SEQ*HD];   // attention out, flat [4096][512]
__device__ __align__(16) uint16_t g_Al [NG*SEQ*HD];
__device__ __align__(16) uint16_t g_Wh [EMB*EMB];
__device__ __align__(16) uint16_t g_Wl [EMB*EMB];

// ---- helpers ----
__device__ __forceinline__ void split2(float x0, float x1, uint32_t& h, uint32_t& l){
    asm("cvt.rn.bf16x2.f32 %0, %1, %2;" : "=r"(h) : "f"(x1), "f"(x0));
    float h0 = __uint_as_float(h << 16);
    float h1 = __uint_as_float(h & 0xffff0000u);
    float l0 = x0 - h0, l1 = x1 - h1;
    asm("cvt.rn.bf16x2.f32 %0, %1, %2;" : "=r"(l) : "f"(l1), "f"(l0));
}
__device__ __forceinline__ void mma_bf16(float* d, const uint32_t* a, const uint32_t* b){
    asm volatile("mma.sync.aligned.m16n8k16.row.col.f32.bf16.bf16.f32 "
        "{%0,%1,%2,%3}, {%4,%5,%6,%7}, {%8,%9}, {%0,%1,%2,%3};"
        : "+f"(d[0]), "+f"(d[1]), "+f"(d[2]), "+f"(d[3])
        : "r"(a[0]), "r"(a[1]), "r"(a[2]), "r"(a[3]), "r"(b[0]), "r"(b[1]));
}
__device__ __forceinline__ float ex2(float x){
    float r; asm("ex2.approx.f32 %0, %1;" : "=f"(r) : "f"(x)); return r;
}
__device__ __forceinline__ uint32_t smem_u32(const void* p){
    uint32_t a;
    asm("{ .reg .u64 t; cvta.to.shared.u64 t, %1; cvt.u32.u64 %0, t; }" : "=r"(a) : "l"(p));
    return a;
}
#define LDSM4(r, a) \
    asm volatile("ldmatrix.sync.aligned.m8n8.x4.shared.b16 {%0,%1,%2,%3}, [%4];" \
        : "=r"((r)[0]), "=r"((r)[1]), "=r"((r)[2]), "=r"((r)[3]) : "r"(a))
__device__ __forceinline__ void cp16(uint32_t dst, const void* src){
    asm volatile("cp.async.cg.shared.global [%0], [%1], 16;" :: "r"(dst), "l"(src));
}
#define CP_COMMIT() asm volatile("cp.async.commit_group;" ::: "memory")
#define CP_WAIT(n)  asm volatile("cp.async.wait_group %0;" :: "n"(n) : "memory")

// scalar-LDS frag loads (proj)
__device__ __forceinline__ void lda(uint32_t* a, const char* base, uint32_t off){
    a[0] = *(const uint32_t*)(base + off);
    a[1] = *(const uint32_t*)(base + off + PITCH*16u);
    a[2] = *(const uint32_t*)(base + off + 16u);
    a[3] = *(const uint32_t*)(base + off + PITCH*16u + 16u);
}
__device__ __forceinline__ void ldb(uint32_t* b, const char* base, uint32_t off){
    b[0] = *(const uint32_t*)(base + off);
    b[1] = *(const uint32_t*)(base + off + 16u);
}

// attn smem: QH[256x144] QL | K/V TRIPLE-buffer ring
#define QH_O 0u
#define QL_O 36864u
#define KV_O 73728u
#define KVB  36864u        // per buffer: KH 0 | KL 9216 | VH 18432 | VL 27648
#define SMEM_ATT 184320u   // 73728 + 3*36864

// proj smem
#define PJ_XH 0u
#define PJ_XL 18432u
#define PJ_WH 36864u
#define PJ_WL 46080u
#define PJ_BYTES 55296u     // staging tile 128x65 f32 = 33280 fits

// fc smem (128x128 tile, 512 thr): TRIPLE-buffer ring of 73728
#define FC_AH 0u
#define FC_AL 18432u
#define FC_BH 36864u
#define FC_BL 55296u
#define FC_BUF 73728u
#define FC_BYTES 221184u   // 3 * 73728

// ---------------------------------------------------------------------------
// QKV projection via mma + fused Wfc split (blockIdx.y == 3).
// Outputs staged through smem f32 tile, stored with coalesced 16B writes.
// ---------------------------------------------------------------------------
__global__ __launch_bounds__(256) void proj_k(
    const float* __restrict__ q, const float* __restrict__ k, const float* __restrict__ v,
    const float* __restrict__ Wq, const float* __restrict__ Wk, const float* __restrict__ Wv,
    const float* __restrict__ Wfc)
{
    extern __shared__ __align__(16) char smem[];
    const int which = blockIdx.y;
    const int t = threadIdx.x;

    if (which == 3){   // Wfc -> split bf16 (fused prep)
        int i = (blockIdx.x*256 + t)*4;
        float4 x = *(const float4*)&Wfc[i];
        uint32_t h0,l0,h1,l1;
        split2(x.x, x.y, h0, l0); split2(x.z, x.w, h1, l1);
        *(uint2*)&((uint32_t*)g_Wh)[i>>1] = make_uint2(h0,h1);
        *(uint2*)&((uint32_t*)g_Wl)[i>>1] = make_uint2(l0,l1);
        return;
    }

    const int lane = t & 31, wid = t >> 5;
    const int r4 = lane >> 2, c2 = lane & 3;
    const int m0 = (wid >> 1) * 32;
    const int n0 = (wid & 1) * 32;
    const float* X = which==0 ? q  : (which==1 ? k  : v);
    const float* W = which==0 ? Wq : (which==1 ? Wk : Wv);
    const size_t rb = (size_t)blockIdx.x * 128;

    {
        const int row = t >> 1, cg = (t & 1) * 32;
        const float* src = X + (rb + row)*HD + cg;
        #pragma unroll
        for (int j=0;j<8;j++){
            float4 x = *(const float4*)&src[j*4];
            uint32_t h0,l0,h1,l1;
            split2(x.x, x.y, h0, l0); split2(x.z, x.w, h1, l1);
            uint32_t off = (uint32_t)(row*PITCH + cg + j*4)*2u;
            *(uint2*)(smem + PJ_XH + off) = make_uint2(h0,h1);
            *(uint2*)(smem + PJ_XL + off) = make_uint2(l0,l1);
        }
    }
    {
        const int row = t >> 2, cg = (t & 3) * 16;
        const float* src = W + row*HD + cg;
        #pragma unroll
        for (int j=0;j<4;j++){
            float4 x = *(const float4*)&src[j*4];
            uint32_t h0,l0,h1,l1;
            split2(x.x, x.y, h0, l0); split2(x.z, x.w, h1, l1);
            uint32_t off = (uint32_t)(row*PITCH + cg + j*4)*2u;
            *(uint2*)(smem + PJ_WH + off) = make_uint2(h0,h1);
            *(uint2*)(smem + PJ_WL + off) = make_uint2(l0,l1);
        }
    }
    __syncthreads();

    float acc[2][4][4] = {};
    #pragma unroll
    for (int ksz=0; ksz<4; ksz++){
        const int kc = ksz*16;
        uint32_t ah[2][4], al[2][4], bh[4][2], bl[4][2];
        #pragma unroll
        for (int mf=0; mf<2; mf++){
            uint32_t off = (uint32_t)((m0+16*mf+r4)*PITCH + kc + 2*c2)*2u;
            lda(ah[mf], smem + PJ_XH, off);
            lda(al[mf], smem + PJ_XL, off);
        }
        #pragma unroll
        for (int nf=0; nf<4; nf++){
            uint32_t off = (uint32_t)((n0+8*nf+r4)*PITCH + kc + 2*c2)*2u;
            ldb(bh[nf], smem + PJ_WH, off);
            ldb(bl[nf], smem + PJ_WL, off);
        }
        #pragma unroll
        for (int mf=0; mf<2; mf++)
            #pragma unroll
            for (int nf=0; nf<4; nf++){
                mma_bf16(acc[mf][nf], ah[mf], bh[nf]);
                mma_bf16(acc[mf][nf], ah[mf], bl[nf]);
                mma_bf16(acc[mf][nf], al[mf], bh[nf]);
            }
    }

    // ---- stage result tile in smem f32 [128][65] ----
    __syncthreads();
    float* tile = (float*)smem;
    #pragma unroll
    for (int mf=0; mf<2; mf++)
        #pragma unroll
        for (int nf=0; nf<4; nf++){
            int rl = m0 + 16*mf + r4;
            int col = n0 + 8*nf + 2*c2;
            tile[rl*65 + col]       = acc[mf][nf][0];
            tile[rl*65 + col+1]     = acc[mf][nf][1];
            tile[(rl+8)*65 + col]   = acc[mf][nf][2];
            tile[(rl+8)*65 + col+1] = acc[mf][nf][3];
        }
    __syncthreads();

    if (which == 2){
        const int g  = (int)(rb >> 11);
        const int s0 = (int)(rb & 2047);
        const int d  = t >> 2, sq = (t & 3) * 32;
        const size_t base = ((size_t)g*HD + d)*SEQ + s0 + sq;
        #pragma unroll
        for (int j8=0; j8<4; j8++){
            float f[8];
            #pragma unroll
            for (int i=0;i<8;i++) f[i] = tile[(sq + j8*8 + i)*65 + d];
            uint32_t h[4], l[4];
            split2(f[0],f[1],h[0],l[0]); split2(f[2],f[3],h[1],l[1]);
            split2(f[4],f[5],h[2],l[2]); split2(f[6],f[7],h[3],l[3]);
            *(uint4*)&((uint32_t*)g_Vth)[(base + j8*8)>>1] = make_uint4(h[0],h[1],h[2],h[3]);
            *(uint4*)&((uint32_t*)g_Vtl)[(base + j8*8)>>1] = make_uint4(l[0],l[1],l[2],l[3]);
        }
    } else {
        uint32_t* dh = (uint32_t*)(which==0 ? g_Qh : g_Kh);
        uint32_t* dl = (uint32_t*)(which==0 ? g_Ql : g_Kl);
        const float sc = (which==0) ? QSCALE : 1.0f;
        const int row = t >> 1, cg = (t & 1) * 32;
        const size_t base = ((rb + row)*HD + cg) >> 1;
        const float* trow = tile + row*65 + cg;
        #pragma unroll
        for (int j8=0; j8<4; j8++){
            float f[8];
            #pragma unroll
            for (int i=0;i<8;i++) f[i] = trow[j8*8 + i]*sc;
            uint32_t h[4], l[4];
            split2(f[0],f[1],h[0],l[0]); split2(f[2],f[3],h[1],l[1]);
            split2(f[4],f[5],h[2],l[2]); split2(f[6],f[7],h[3],l[3]);
            *(uint4*)&dh[base + j8*4] = make_uint4(h[0],h[1],h[2],h[3]);
            *(uint4*)&dl[base + j8*4] = make_uint4(l[0],l[1],l[2],l[3]);
        }
    }
}

// ---------------------------------------------------------------------------
// Flash attention: 8 warps x 32 q-rows, register P, cp.async K/V on a
// 3-stage ring -> ONE barrier per iteration (write of buf[(kt+1)%3] is
// ordered vs its last read (iter kt-2) by the top barrier of iter kt-1).
// grid = (8, 16), 256 threads, 1 CTA/SM.
// ---------------------------------------------------------------------------
__global__ __launch_bounds__(256, 1) void attn_k()
{
    extern __shared__ __align__(16) char smem[];
    const uint32_t sb = smem_u32(smem);
    const int t    = threadIdx.x;
    const int lane = t & 31, wid = t >> 5;
    const int r4 = lane >> 2, c2 = lane & 3;
    const int m0 = wid * 32;
    const int g  = blockIdx.y;
    const int q0 = blockIdx.x * BQ;

    const uint32_t a_off0 = (uint32_t)(m0 + (lane & 15)) * PITCHB + ((lane & 16) ? 16u : 0u);
    const uint32_t a_off1 = a_off0 + 16u*PITCHB;
    const uint32_t b_off  = (uint32_t)((lane & 7) + ((lane & 16) ? 8 : 0)) * PITCHB
                          + ((lane & 8) ? 16u : 0u);

    const int krow = t >> 2, kc = (t & 3) * 16;
    const uint32_t dko = (uint32_t)(krow*PITCH + kc)*2u;

    // ---- issue tile 0 into ring slot 0 ----
    {
        const size_t kg = (size_t)(g*SEQ + krow)*HD + kc;
        const size_t vg = ((size_t)g*HD + krow)*SEQ + kc;
        uint32_t d = sb + KV_O + dko;
        cp16(d,            g_Kh  + kg); cp16(d + 16u,          g_Kh  + kg + 8);
        cp16(d + 9216u,    g_Kl  + kg); cp16(d + 9216u + 16u,  g_Kl  + kg + 8);
        cp16(d + 18432u,   g_Vth + vg); cp16(d + 18432u + 16u, g_Vth + vg + 8);
        cp16(d + 27648u,   g_Vtl + vg); cp16(d + 27648u + 16u, g_Vtl + vg + 8);
        CP_COMMIT();
    }

    // ---- load Q tile (256 rows, one FULL 128B row per thread) ----
    {
        const uint16_t* qh = g_Qh + ((size_t)(g*SEQ + q0 + t))*HD;
        const uint16_t* ql = g_Ql + ((size_t)(g*SEQ + q0 + t))*HD;
        uint32_t off = (uint32_t)t * PITCHB;
        #pragma unroll
        for (int j=0;j<8;j++){
            *(uint4*)(smem + QH_O + off + j*16u) = *(const uint4*)(qh + j*8);
            *(uint4*)(smem + QL_O + off + j*16u) = *(const uint4*)(ql + j*8);
        }
    }

    float oacc[2][8][4] = {};
    float ls[2][2] = {};

    int cur = 0, nxt = 1;   // ring indices
    for (int kt = 0; kt < NKT; kt++){
        if (kt + 1 < NKT){
            const size_t kg = (size_t)(g*SEQ + (kt+1)*BK + krow)*HD + kc;
            const size_t vg = ((size_t)g*HD + krow)*SEQ + (kt+1)*BK + kc;
            uint32_t d = sb + KV_O + (uint32_t)nxt*KVB + dko;
            cp16(d,            g_Kh  + kg); cp16(d + 16u,          g_Kh  + kg + 8);
            cp16(d + 9216u,    g_Kl  + kg); cp16(d + 9216u + 16u,  g_Kl  + kg + 8);
            cp16(d + 18432u,   g_Vth + vg); cp16(d + 18432u + 16u, g_Vth + vg + 8);
            cp16(d + 27648u,   g_Vtl + vg); cp16(d + 27648u + 16u, g_Vtl + vg + 8);
            CP_COMMIT();
            CP_WAIT(1);
        } else {
            CP_WAIT(0);
        }
        __syncthreads();   // tile kt visible (and Q on first iter); orders ring reuse

        const uint32_t kvb = sb + KV_O + (uint32_t)cur*KVB;

        // ---- S = Q K^T: K frags loaded once, feed both row groups ----
        float sacc[2][8][4] = {};
        #pragma unroll
        for (int ksz=0; ksz<4; ksz++){
            const uint32_t kb = (uint32_t)ksz * 32u;
            uint32_t qh0[4], ql0[4], qh1[4], ql1[4];
            LDSM4(qh0, sb + QH_O + a_off0 + kb);
            LDSM4(ql0, sb + QL_O + a_off0 + kb);
            LDSM4(qh1, sb + QH_O + a_off1 + kb);
            LDSM4(ql1, sb + QL_O + a_off1 + kb);
            #pragma unroll
            for (int np=0; np<4; np++){
                uint32_t bh[4], bl[4];
                LDSM4(bh, kvb + (uint32_t)np*2304u + b_off + kb);
                LDSM4(bl, kvb + 9216u + (uint32_t)np*2304u + b_off + kb);
                mma_bf16(sacc[0][2*np  ], qh0, bh);
                mma_bf16(sacc[0][2*np  ], qh0, bl);
                mma_bf16(sacc[0][2*np  ], ql0, bh);
                mma_bf16(sacc[0][2*np+1], qh0, bh+2);
                mma_bf16(sacc[0][2*np+1], qh0, bl+2);
                mma_bf16(sacc[0][2*np+1], ql0, bh+2);
                mma_bf16(sacc[1][2*np  ], qh1, bh);
                mma_bf16(sacc[1][2*np  ], qh1, bl);
                mma_bf16(sacc[1][2*np  ], ql1, bh);
                mma_bf16(sacc[1][2*np+1], qh1, bh+2);
                mma_bf16(sacc[1][2*np+1], qh1, bl+2);
                mma_bf16(sacc[1][2*np+1], ql1, bh+2);
            }
        }

        // ---- fused softmax + PV per 16-key chunk ----
        #pragma unroll
        for (int ks2=0; ks2<4; ks2++){
            uint32_t pah[2][4], pal[2][4];
            #pragma unroll
            for (int mg=0; mg<2; mg++){
                #pragma unroll
                for (int j=0;j<2;j++){
                    const int nf = 2*ks2 + j;
                    float p0 = ex2(sacc[mg][nf][0]), p1 = ex2(sacc[mg][nf][1]);
                    float p2 = ex2(sacc[mg][nf][2]), p3 = ex2(sacc[mg][nf][3]);
                    ls[mg][0] += p0 + p1;
                    ls[mg][1] += p2 + p3;
                    split2(p0, p1, pah[mg][2*j  ], pal[mg][2*j  ]);
                    split2(p2, p3, pah[mg][2*j+1], pal[mg][2*j+1]);
                }
            }
            const uint32_t kb = (uint32_t)ks2 * 32u;
            #pragma unroll
            for (int np=0; np<4; np++){
                uint32_t bh[4], bl[4];
                LDSM4(bh, kvb + 18432u + (uint32_t)np*2304u + b_off + kb);
                LDSM4(bl, kvb + 27648u + (uint32_t)np*2304u + b_off + kb);
                #pragma unroll
                for (int mg=0; mg<2; mg++){
                    mma_bf16(oacc[mg][2*np  ], pah[mg], bh);
                    mma_bf16(oacc[mg][2*np  ], pah[mg], bl);
                    mma_bf16(oacc[mg][2*np  ], pal[mg], bh);
                    mma_bf16(oacc[mg][2*np+1], pah[mg], bh+2);
                    mma_bf16(oacc[mg][2*np+1], pah[mg], bl+2);
                    mma_bf16(oacc[mg][2*np+1], pal[mg], bh+2);
                }
            }
        }
        // no trailing barrier: ring slot written next is 2 iters stale
        cur = nxt; nxt = (nxt == 2) ? 0 : nxt + 1;
    }

    // ---- row sums over c2 lanes ----
    #pragma unroll
    for (int mg=0; mg<2; mg++)
        #pragma unroll
        for (int i=0;i<2;i++){
            ls[mg][i] += __shfl_xor_sync(0xffffffffu, ls[mg][i], 1);
            ls[mg][i] += __shfl_xor_sync(0xffffffffu, ls[mg][i], 2);
        }

    // ---- write O / lsum, pre-split for fc ----
    uint32_t* ah32 = (uint32_t*)g_Ah;
    uint32_t* al32 = (uint32_t*)g_Al;
    #pragma unroll
    for (int mg=0; mg<2; mg++){
        const int row = q0 + m0 + mg*16 + r4;
        const float inv0 = 1.0f / ls[mg][0], inv1 = 1.0f / ls[mg][1];
        #pragma unroll
        for (int nf=0; nf<8; nf++){
            int col = 8*nf + 2*c2;
            uint32_t h, l;
            split2(oacc[mg][nf][0]*inv0, oacc[mg][nf][1]*inv0, h, l);
            size_t idx = (((size_t)(g*SEQ + row))*HD + col) >> 1;
            ah32[idx] = h; al32[idx] = l;
            split2(oacc[mg][nf][2]*inv1, oacc[mg][nf][3]*inv1, h, l);
            idx = (((size_t)(g*SEQ + row + 8))*HD + col) >> 1;
            ah32[idx] = h; al32[idx] = l;
        }
    }
}

// ---------------------------------------------------------------------------
// FC: 512 threads, 128x128 tiles, 16 warps (4m x 4n of 32x32), cp.async on a
// 3-stage ring -> one barrier per chunk. grid = (4, 32) = 128 CTAs, 1 CTA/SM.
// ---------------------------------------------------------------------------
__global__ __launch_bounds__(512, 1) void fc_k(const float* __restrict__ bfc,
                                               float* __restrict__ out)
{
    extern __shared__ __align__(16) char smem[];
    const uint32_t sb = smem_u32(smem);
    const int t    = threadIdx.x;
    const int lane = t & 31, wid = t >> 5;
    const int r4 = lane >> 2, c2 = lane & 3;
    const int m0 = (wid >> 2) * 32;
    const int n0 = (wid & 3) * 32;
    const int eb = blockIdx.x * 128;
    const size_t rb = (size_t)blockIdx.y * 128;

    const uint32_t a_off0 = (uint32_t)(m0 + (lane & 15)) * PITCHB + ((lane & 16) ? 16u : 0u);
    const uint32_t a_off1 = a_off0 + 16u*PITCHB;
    const uint32_t b_off  = (uint32_t)(n0 + (lane & 7) + ((lane & 16) ? 8 : 0)) * PITCHB
                          + ((lane & 8) ? 16u : 0u);

    // per-thread cp.async coordinates (A and B both 128 rows x 64 k, 512 thr)
    const int arow = t >> 2, acg = (t & 3) * 16;
    const uint32_t dao = (uint32_t)(arow*PITCH + acg)*2u;

    // issue chunk 0 into ring slot 0
    {
        const uint16_t* ah = g_Ah + (rb + arow)*EMB + acg;
        const uint16_t* al = g_Al + (rb + arow)*EMB + acg;
        const uint16_t* bh = g_Wh + (size_t)(eb + arow)*EMB + acg;
        const uint16_t* bl = g_Wl + (size_t)(eb + arow)*EMB + acg;
        #pragma unroll
        for (int j=0;j<2;j++){
            cp16(sb + FC_AH + dao + j*16u, ah + j*8);
            cp16(sb + FC_AL + dao + j*16u, al + j*8);
            cp16(sb + FC_BH + dao + j*16u, bh + j*8);
            cp16(sb + FC_BL + dao + j*16u, bl + j*8);
        }
        CP_COMMIT();
    }

    float acc[2][4][4] = {};
    int cur = 0, nxt = 1;

    for (int kc2 = 0; kc2 < 8; kc2++){
        if (kc2 + 1 < 8){
            const int f1 = (kc2+1) * 64;
            const uint16_t* ah = g_Ah + (rb + arow)*EMB + f1 + acg;
            const uint16_t* al = g_Al + (rb + arow)*EMB + f1 + acg;
            const uint16_t* bh = g_Wh + (size_t)(eb + arow)*EMB + f1 + acg;
            const uint16_t* bl = g_Wl + (size_t)(eb + arow)*EMB + f1 + acg;
            uint32_t d = sb + (uint32_t)nxt*FC_BUF;
            #pragma unroll
            for (int j=0;j<2;j++){
                cp16(d + FC_AH + dao + j*16u, ah + j*8);
                cp16(d + FC_AL + dao + j*16u, al + j*8);
                cp16(d + FC_BH + dao + j*16u, bh + j*8);
                cp16(d + FC_BL + dao + j*16u, bl + j*8);
            }
            CP_COMMIT();
            CP_WAIT(1);
        } else {
            CP_WAIT(0);
        }
        __syncthreads();   // chunk kc2 visible; orders ring reuse

        const uint32_t buf = sb + (uint32_t)cur*FC_BUF;

        #pragma unroll
        for (int ksz=0; ksz<4; ksz++){
            const uint32_t kb = (uint32_t)ksz * 32u;
            uint32_t ah0[4], al0[4], ah1[4], al1[4], bh[4], bl[4];
            LDSM4(ah0, buf + FC_AH + a_off0 + kb);
            LDSM4(al0, buf + FC_AL + a_off0 + kb);
            LDSM4(ah1, buf + FC_AH + a_off1 + kb);
            LDSM4(al1, buf + FC_AL + a_off1 + kb);
            LDSM4(bh,  buf + FC_BH + b_off + kb);
            LDSM4(bl,  buf + FC_BL + b_off + kb);
            uint32_t bh2[4], bl2[4];
            LDSM4(bh2, buf + FC_BH + 16u*PITCHB + b_off + kb);
            LDSM4(bl2, buf + FC_BL + 16u*PITCHB + b_off + kb);

            mma_bf16(acc[0][0], ah0, bh);   mma_bf16(acc[0][0], ah0, bl);   mma_bf16(acc[0][0], al0, bh);
            mma_bf16(acc[0][1], ah0, bh+2); mma_bf16(acc[0][1], ah0, bl+2); mma_bf16(acc[0][1], al0, bh+2);
            mma_bf16(acc[0][2], ah0, bh2);  mma_bf16(acc[0][2], ah0, bl2);  mma_bf16(acc[0][2], al0, bh2);
            mma_bf16(acc[0][3], ah0, bh2+2);mma_bf16(acc[0][3], ah0, bl2+2);mma_bf16(acc[0][3], al0, bh2+2);
            mma_bf16(acc[1][0], ah1, bh);   mma_bf16(acc[1][0], ah1, bl);   mma_bf16(acc[1][0], al1, bh);
            mma_bf16(acc[1][1], ah1, bh+2); mma_bf16(acc[1][1], ah1, bl+2); mma_bf16(acc[1][1], al1, bh+2);
            mma_bf16(acc[1][2], ah1, bh2);  mma_bf16(acc[1][2], ah1, bl2);  mma_bf16(acc[1][2], al1, bh2);
            mma_bf16(acc[1][3], ah1, bh2+2);mma_bf16(acc[1][3], ah1, bl2+2);mma_bf16(acc[1][3], al1, bh2+2);
        }
        // no trailing barrier (3-stage ring)
        cur = nxt; nxt = (nxt == 2) ? 0 : nxt + 1;
    }

    #pragma unroll
    for (int mf=0; mf<2; mf++)
        #pragma unroll
        for (int nf=0; nf<4; nf++){
            int row = (int)rb + m0 + 16*mf + r4;
            int col = eb + n0 + 8*nf + 2*c2;
            float2 b = *(const float2*)&bfc[col];
            *(float2*)&out[(size_t)row*EMB + col] =
                make_float2(acc[mf][nf][0]+b.x, acc[mf][nf][1]+b.y);
            *(float2*)&out[(size_t)(row+8)*EMB + col] =
                make_float2(acc[mf][nf][2]+b.x, acc[mf][nf][3]+b.y);
        }
}

// ---------------------------------------------------------------------------
extern "C" void kernel_launch(void* const* d_in, const int* in_sizes, int n_in,
                              void* d_out, int out_size)
{
    (void)in_sizes; (void)n_in; (void)out_size;
    const float* q   = (const float*)d_in[0];
    const float* k   = (const float*)d_in[1];
    const float* v   = (const float*)d_in[2];
    const float* Wq  = (const float*)d_in[3];
    const float* Wk  = (const float*)d_in[4];
    const float* Wv  = (const float*)d_in[5];
    const float* Wfc = (const float*)d_in[6];
    const float* bfc = (const float*)d_in[7];
    float* out = (float*)d_out;

    static int smem_set = 0;
    if (!smem_set){
        cudaFuncSetAttribute(attn_k, cudaFuncAttributeMaxDynamicSharedMemorySize, SMEM_ATT);
        cudaFuncSetAttribute(proj_k, cudaFuncAttributeMaxDynamicSharedMemorySize, PJ_BYTES);
        cudaFuncSetAttribute(fc_k,   cudaFuncAttributeMaxDynamicSharedMemorySize, FC_BYTES);
        smem_set = 1;
    }

    proj_k<<<dim3(256,4), 256, PJ_BYTES>>>(q, k, v, Wq, Wk, Wv, Wfc);
    attn_k<<<dim3(SEQ/BQ, NG), 256, SMEM_ATT>>>();
    fc_k  <<<dim3(4,32), 512, FC_BYTES>>>(bfc, out);
}